// round 10
// baseline (speedup 1.0000x reference)
#include <cuda_runtime.h>
#include <cuda_bf16.h>
#include <cstdint>

// ---------------------------------------------------------------------------
// GLA block: B=8, T=4096, D=1024, H=4, Dk=128, Dv=256
// GEMMs: mma.sync bf16 3-term split.
// This round: GEMM fragment double-buffering (LDSM latency hiding) +
// 4-stage smem pipeline. Topology unchanged (proven R6/R9).
// ---------------------------------------------------------------------------

#define BB   8
#define TT   4096
#define MM   (BB*TT)          // 32768
#define QSCALE 0.08838834764831845f
#define NPACK 3584            // packed q|k|decay|v|g

// ---------------- scratch (device globals; allocation-free) ----------------
__device__ __nv_bfloat16 g_xh[MM*1024], g_xl[MM*1024];
__device__ __nv_bfloat16 g_wah[1024*NPACK], g_wal[1024*NPACK];   // Wq|Wk|Weff|Wv|Wg
__device__ __nv_bfloat16 g_w_oh[1024*1024], g_w_ol[1024*1024];   // Wo
__device__ float g_q[MM*512], g_k[MM*512], g_dcy[MM*512];
__device__ float g_v[MM*1024], g_g[MM*1024], g_o[MM*1024];
__device__ __nv_bfloat16 g_oh[MM*1024], g_ol[MM*1024];

__device__ __forceinline__ void cp16(uint32_t s, const void* g) {
    asm volatile("cp.async.cg.shared.global [%0], [%1], 16;" :: "r"(s), "l"(g));
}

// ---------------------------------------------------------------------------
// fp32 -> (bf16 hi, lo) split helpers
// ---------------------------------------------------------------------------
__device__ __forceinline__ void split8(const float* f, uint32_t* hp, uint32_t* lp)
{
#pragma unroll
    for (int j = 0; j < 4; j++) {
        __nv_bfloat16 h0 = __float2bfloat16_rn(f[2*j]);
        __nv_bfloat16 h1 = __float2bfloat16_rn(f[2*j+1]);
        __nv_bfloat162 hh = __halves2bfloat162(h0, h1);
        __nv_bfloat162 ll = __halves2bfloat162(
            __float2bfloat16_rn(f[2*j]   - __bfloat162float(h0)),
            __float2bfloat16_rn(f[2*j+1] - __bfloat162float(h1)));
        hp[j] = *(uint32_t*)&hh;
        lp[j] = *(uint32_t*)&ll;
    }
}

__global__ void split_kernel(const float* __restrict__ s,
                             __nv_bfloat16* __restrict__ h,
                             __nv_bfloat16* __restrict__ l, int n)
{
    int i = (blockIdx.x * blockDim.x + threadIdx.x) * 16;
    if (i >= n) return;
    float4 v0 = *(const float4*)(s + i);
    float4 v1 = *(const float4*)(s + i + 4);
    float4 v2 = *(const float4*)(s + i + 8);
    float4 v3 = *(const float4*)(s + i + 12);
    float f[16] = {v0.x, v0.y, v0.z, v0.w, v1.x, v1.y, v1.z, v1.w,
                   v2.x, v2.y, v2.z, v2.w, v3.x, v3.y, v3.z, v3.w};
    uint32_t hp[4], lp[4];
    split8(f, hp, lp);
    *(uint4*)(h + i) = make_uint4(hp[0], hp[1], hp[2], hp[3]);
    *(uint4*)(l + i) = make_uint4(lp[0], lp[1], lp[2], lp[3]);
    split8(f + 8, hp, lp);
    *(uint4*)(h + i + 8) = make_uint4(hp[0], hp[1], hp[2], hp[3]);
    *(uint4*)(l + i + 8) = make_uint4(lp[0], lp[1], lp[2], lp[3]);
}

__global__ void psplit_kernel(const float* __restrict__ src, int Nsrc,
                              int coloff, int total)
{
    int i = (blockIdx.x * blockDim.x + threadIdx.x) * 8;
    if (i >= total) return;
    int k = i / Nsrc, n = i % Nsrc;
    float4 v0 = *(const float4*)(src + i);
    float4 v1 = *(const float4*)(src + i + 4);
    float f[8] = {v0.x, v0.y, v0.z, v0.w, v1.x, v1.y, v1.z, v1.w};
    uint32_t hp[4], lp[4];
    split8(f, hp, lp);
    size_t o = (size_t)k * NPACK + coloff + n;
    *(uint4*)(g_wah + o) = make_uint4(hp[0], hp[1], hp[2], hp[3]);
    *(uint4*)(g_wal + o) = make_uint4(lp[0], lp[1], lp[2], lp[3]);
}

__global__ void weff_psplit_kernel(const float* __restrict__ w1,
                                   const float* __restrict__ w2)
{
    int idx = blockIdx.x * blockDim.x + threadIdx.x;   // k*512 + n
    int kk = idx >> 9, n = idx & 511;
    float s = 0.f;
#pragma unroll
    for (int r = 0; r < 16; r++)
        s += w1[kk * 16 + r] * w2[r * 512 + n];
    __nv_bfloat16 h = __float2bfloat16_rn(s);
    size_t o = (size_t)kk * NPACK + 1024 + n;
    g_wah[o] = h;
    g_wal[o] = __float2bfloat16_rn(s - __bfloat162float(h));
}

// ---------------------------------------------------------------------------
// bf16 split-GEMM, 4-stage cp.async pipeline + register fragment
// double-buffering. FUSED=1: packed epilogue routing (q|k|decay|v|g).
// ---------------------------------------------------------------------------
#define A_T 5120
#define B_T 4352
#define STG_E (2*A_T + 2*B_T)
#define SMEM4 (4 * STG_E * 2)          // 151552 B

#define LDSM_X4(R0,R1,R2,R3,ADDR) \
    asm volatile("ldmatrix.sync.aligned.m8n8.x4.shared.b16 {%0,%1,%2,%3}, [%4];" \
        : "=r"(R0),"=r"(R1),"=r"(R2),"=r"(R3) : "r"(ADDR))
#define LDSM_X4T(R0,R1,R2,R3,ADDR) \
    asm volatile("ldmatrix.sync.aligned.m8n8.x4.trans.shared.b16 {%0,%1,%2,%3}, [%4];" \
        : "=r"(R0),"=r"(R1),"=r"(R2),"=r"(R3) : "r"(ADDR))
#define MMA(D,A,B) \
    asm volatile("mma.sync.aligned.m16n8k16.row.col.f32.bf16.bf16.f32 " \
        "{%0,%1,%2,%3}, {%4,%5,%6,%7}, {%8,%9}, {%0,%1,%2,%3};" \
        : "+f"(D[0]),"+f"(D[1]),"+f"(D[2]),"+f"(D[3]) \
        : "r"(A[0]),"r"(A[1]),"r"(A[2]),"r"(A[3]),"r"(B[0]),"r"(B[1]))

template<int FUSED>
__global__ __launch_bounds__(256)
void hgemm3(const __nv_bfloat16* __restrict__ Ah, const __nv_bfloat16* __restrict__ Al,
            const __nv_bfloat16* __restrict__ Bh, const __nv_bfloat16* __restrict__ Bl,
            float* __restrict__ C, int K, int ldB, float scale,
            const float* __restrict__ bias,
            float* __restrict__ pq, float* __restrict__ pk, float* __restrict__ pd,
            float* __restrict__ pv, float* __restrict__ pgg)
{
    extern __shared__ __align__(16) __nv_bfloat16 sm[];

    const int tid = threadIdx.x;
    const int bn = blockIdx.x, bm = blockIdx.y;
    const int lane = tid & 31, wid = tid >> 5;
    const int wm = (wid & 1) * 64;
    const int wn = (wid >> 1) * 32;

    const int ar = tid >> 2, ac = (tid & 3) * 8;
    const int br = tid >> 4, bc = (tid & 15) * 8;

    const __nv_bfloat16* gAh = Ah + (size_t)(bm*128 + ar) * K + ac;
    const __nv_bfloat16* gAl = Al + (size_t)(bm*128 + ar) * K + ac;
    const __nv_bfloat16* gBh = Bh + (size_t)br * ldB + bn*128 + bc;
    const __nv_bfloat16* gBl = Bl + (size_t)br * ldB + bn*128 + bc;

    const uint32_t u0 = (uint32_t)__cvta_generic_to_shared(sm);
    const uint32_t a_st0 = (ar*40 + ac)*2, a_st1 = ((ar+64)*40 + ac)*2;
    const uint32_t b_st0 = (br*136 + bc)*2, b_st1 = ((br+16)*136 + bc)*2;

    float acc[4][4][4];
#pragma unroll
    for (int i = 0; i < 4; i++)
#pragma unroll
        for (int j = 0; j < 4; j++)
#pragma unroll
            for (int r = 0; r < 4; r++) acc[i][j][r] = 0.f;

    const int KT = K >> 5;

    auto load_stage = [&](int kt, int st) {
        const __nv_bfloat16* pAh = gAh + kt*32;
        const __nv_bfloat16* pAl = gAl + kt*32;
        const __nv_bfloat16* pBh = gBh + (size_t)kt*32*ldB;
        const __nv_bfloat16* pBl = gBl + (size_t)kt*32*ldB;
        uint32_t sb = u0 + (uint32_t)st * (STG_E*2);
        cp16(sb + a_st0, pAh);
        cp16(sb + a_st1, pAh + (size_t)64*K);
        cp16(sb + A_T*2 + a_st0, pAl);
        cp16(sb + A_T*2 + a_st1, pAl + (size_t)64*K);
        cp16(sb + 4*A_T + b_st0, pBh);
        cp16(sb + 4*A_T + b_st1, pBh + (size_t)16*ldB);
        cp16(sb + 4*A_T + 2*B_T + b_st0, pBl);
        cp16(sb + 4*A_T + 2*B_T + b_st1, pBl + (size_t)16*ldB);
        asm volatile("cp.async.commit_group;");
    };

    const int arow = wm + (lane & 15);
    const int acol = (lane >> 4) * 8;
    const int bkr  = (lane & 15);
    const int bcol = wn + ((lane >> 4) * 8);

    // double-buffered fragments: buf0 = ks0, buf1 = ks1
    uint32_t ahf[2][4][4], alf[2][4][4], bhf[2][4][2], blf[2][4][2];

    auto ldfrag = [&](int buf, uint32_t sb, int ks) {
        uint32_t aBH = sb, aBL = sb + A_T*2;
        uint32_t bBH = sb + 4*A_T, bBL = sb + 4*A_T + 2*B_T;
#pragma unroll
        for (int mi = 0; mi < 4; mi++) {
            uint32_t off = ((arow + mi*16)*40 + ks*16 + acol) * 2;
            LDSM_X4(ahf[buf][mi][0], ahf[buf][mi][1], ahf[buf][mi][2], ahf[buf][mi][3], aBH + off);
            LDSM_X4(alf[buf][mi][0], alf[buf][mi][1], alf[buf][mi][2], alf[buf][mi][3], aBL + off);
        }
#pragma unroll
        for (int p = 0; p < 2; p++) {
            uint32_t off = ((ks*16 + bkr)*136 + bcol + p*16) * 2;
            LDSM_X4T(bhf[buf][2*p][0], bhf[buf][2*p][1], bhf[buf][2*p+1][0], bhf[buf][2*p+1][1], bBH + off);
            LDSM_X4T(blf[buf][2*p][0], blf[buf][2*p][1], blf[buf][2*p+1][0], blf[buf][2*p+1][1], bBL + off);
        }
    };

    auto dommas = [&](int buf) {
#pragma unroll
        for (int mi = 0; mi < 4; mi++)
#pragma unroll
            for (int ni = 0; ni < 4; ni++) MMA(acc[mi][ni], ahf[buf][mi], bhf[buf][ni]);
#pragma unroll
        for (int mi = 0; mi < 4; mi++)
#pragma unroll
            for (int ni = 0; ni < 4; ni++) MMA(acc[mi][ni], ahf[buf][mi], blf[buf][ni]);
#pragma unroll
        for (int mi = 0; mi < 4; mi++)
#pragma unroll
            for (int ni = 0; ni < 4; ni++) MMA(acc[mi][ni], alf[buf][mi], bhf[buf][ni]);
    };

    // prologue: fill 3 stages, stage 0 ready, preload (0, ks0)
    load_stage(0, 0);
    load_stage(1, 1);
    load_stage(2, 2);
    asm volatile("cp.async.wait_group 2;" ::: "memory");
    __syncthreads();
    ldfrag(0, u0, 0);

    for (int kt = 0; kt < KT; kt++) {
        uint32_t sb_cur = u0 + (uint32_t)(kt & 3) * (STG_E*2);
        ldfrag(1, sb_cur, 1);                 // (kt, ks1) while...
        dommas(0);                            // ...MMA (kt, ks0)

        if (kt + 2 < KT)
            asm volatile("cp.async.wait_group 1;" ::: "memory");
        else
            asm volatile("cp.async.wait_group 0;" ::: "memory");
        __syncthreads();
        if (kt + 3 < KT) load_stage(kt + 3, (kt + 3) & 3);
        if (kt + 1 < KT) {
            uint32_t sb_nxt = u0 + (uint32_t)((kt + 1) & 3) * (STG_E*2);
            ldfrag(0, sb_nxt, 0);             // (kt+1, ks0) while...
        }
        dommas(1);                            // ...MMA (kt, ks1)
    }

    float* dst; int ldo, coff, kind; float sc = scale;
    if (FUSED) {
        if      (bn < 4)  { dst = pq;  ldo = 512;  coff = 0;    kind = 0; sc = QSCALE; }
        else if (bn < 8)  { dst = pk;  ldo = 512;  coff = 512;  kind = 1; }
        else if (bn < 12) { dst = pd;  ldo = 512;  coff = 1024; kind = 2; }
        else if (bn < 20) { dst = pv;  ldo = 1024; coff = 1536; kind = 1; }
        else              { dst = pgg; ldo = 1024; coff = 2560; kind = 1; }
    } else {
        dst = C; ldo = ldB; coff = 0; kind = 0;
    }

#pragma unroll
    for (int mi = 0; mi < 4; mi++) {
        int r0 = bm*128 + wm + mi*16 + (lane >> 2);
#pragma unroll
        for (int ni = 0; ni < 4; ni++) {
            int gc = bn*128 + wn + ni*8 + (lane & 3)*2;
            int c = gc - coff;
            float o0 = acc[mi][ni][0], o1 = acc[mi][ni][1];
            float o2 = acc[mi][ni][2], o3 = acc[mi][ni][3];
            if (kind == 0) {
                o0 *= sc; o1 *= sc; o2 *= sc; o3 *= sc;
            } else if (kind == 2) {
                float b0 = bias[c], b1 = bias[c + 1];
                float z, sp;
                z = o0 + b0; sp = fmaxf(-z,0.f) + log1pf(expf(-fabsf(z))); o0 = expf(-sp*0.0625f);
                z = o1 + b1; sp = fmaxf(-z,0.f) + log1pf(expf(-fabsf(z))); o1 = expf(-sp*0.0625f);
                z = o2 + b0; sp = fmaxf(-z,0.f) + log1pf(expf(-fabsf(z))); o2 = expf(-sp*0.0625f);
                z = o3 + b1; sp = fmaxf(-z,0.f) + log1pf(expf(-fabsf(z))); o3 = expf(-sp*0.0625f);
            }
            *(float2*)(dst + (size_t)r0 * ldo + c)       = make_float2(o0, o1);
            *(float2*)(dst + (size_t)(r0 + 8) * ldo + c) = make_float2(o2, o3);
        }
    }
}

// ---------------------------------------------------------------------------
// GLA recurrence (R9 version — proven)
// ---------------------------------------------------------------------------
#define RC 8
#define NCH (TT/RC)

__global__ __launch_bounds__(128)
void gla_rec_kernel()
{
    __shared__ __align__(16) float sq[2][RC*128], sk[2][RC*128], sd[2][RC*128];
    __shared__ __align__(16) float sv[2][RC*32];
    __shared__ float red[2][4][RC*32];

    int bid = blockIdx.x;
    int dvt = bid & 7, h = (bid >> 3) & 3, b = bid >> 5;
    int tid = threadIdx.x, c = tid & 31, w = tid >> 5;

    size_t base_qk = ((size_t)b*TT)*512 + (size_t)h*128;
    size_t base_v  = ((size_t)b*TT)*1024 + (size_t)h*256 + (size_t)dvt*32;
    const float* qp = g_q + base_qk;
    const float* kp = g_k + base_qk;
    const float* dp = g_dcy + base_qk;
    const float* vp = g_v + base_v;
    float* op = g_o + base_v;

    const uint32_t uq = (uint32_t)__cvta_generic_to_shared(&sq[0][0]);
    const uint32_t uk = (uint32_t)__cvta_generic_to_shared(&sk[0][0]);
    const uint32_t ud = (uint32_t)__cvta_generic_to_shared(&sd[0][0]);
    const uint32_t uv = (uint32_t)__cvta_generic_to_shared(&sv[0][0]);

    auto load = [&](int t0, int bf) {
        uint32_t bo = (uint32_t)bf * (RC*128*4);
#pragma unroll
        for (int j = 0; j < 2; j++) {
            int idx = tid + j*128;
            int s = idx >> 5, seg = idx & 31;
            uint32_t so = (uint32_t)((s*128 + seg*4) * 4);
            size_t go = (size_t)(t0 + s)*512 + seg*4;
            cp16(uq + bo + so, qp + go);
            cp16(uk + bo + so, kp + go);
            cp16(ud + bo + so, dp + go);
        }
        if (tid < 64) {
            int s = tid >> 3, seg = tid & 7;
            cp16(uv + (uint32_t)bf*(RC*32*4) + (uint32_t)((s*32 + seg*4)*4),
                 vp + (size_t)(t0 + s)*1024 + seg*4);
        }
        asm volatile("cp.async.commit_group;" ::: "memory");
    };

    unsigned long long S2[16];
#pragma unroll
    for (int i = 0; i < 16; i++) S2[i] = 0ull;

    load(0, 0);
    for (int ci = 0; ci < NCH; ci++) {
        asm volatile("cp.async.wait_group 0;" ::: "memory");
        __syncthreads();
        if (ci + 1 < NCH) load((ci + 1)*RC, (ci + 1) & 1);

        int bf = ci & 1, t0 = ci*RC;
#pragma unroll 2
        for (int s = 0; s < RC; s++) {
            const ulonglong2* q4 = (const ulonglong2*)(&sq[bf][s*128 + w*32]);
            const ulonglong2* k4 = (const ulonglong2*)(&sk[bf][s*128 + w*32]);
            const ulonglong2* d4 = (const ulonglong2*)(&sd[bf][s*128 + w*32]);
            float vj = sv[bf][s*32 + c];
            unsigned long long vv;
            asm("mov.b64 %0, {%1, %1};" : "=l"(vv) : "f"(vj));
            unsigned long long ac[4] = {0ull, 0ull, 0ull, 0ull};
#pragma unroll
            for (int i = 0; i < 8; i++) {
                ulonglong2 qv = q4[i], kv = k4[i], dv = d4[i];
                unsigned long long t;
                asm("mul.rn.f32x2 %0, %1, %2;" : "=l"(t) : "l"(kv.x), "l"(vv));
                asm("fma.rn.f32x2 %0, %1, %2, %3;" : "=l"(S2[2*i])   : "l"(dv.x), "l"(S2[2*i]),   "l"(t));
                asm("fma.rn.f32x2 %0, %1, %2, %3;" : "=l"(ac[(2*i)&3])   : "l"(qv.x), "l"(S2[2*i]),   "l"(ac[(2*i)&3]));
                asm("mul.rn.f32x2 %0, %1, %2;" : "=l"(t) : "l"(kv.y), "l"(vv));
                asm("fma.rn.f32x2 %0, %1, %2, %3;" : "=l"(S2[2*i+1]) : "l"(dv.y), "l"(S2[2*i+1]), "l"(t));
                asm("fma.rn.f32x2 %0, %1, %2, %3;" : "=l"(ac[(2*i+1)&3]) : "l"(qv.y), "l"(S2[2*i+1]), "l"(ac[(2*i+1)&3]));
            }
            float p = 0.f;
#pragma unroll
            for (int j = 0; j < 4; j++) {
                float x0, x1;
                asm("mov.b64 {%0, %1}, %2;" : "=f"(x0), "=f"(x1) : "l"(ac[j]));
                p += x0 + x1;
            }
            red[bf][w][s*32 + c] = p;
        }
        __syncthreads();
#pragma unroll
        for (int j = 0; j < 2; j++) {
            int idx = tid + j*128;
            int s = idx >> 5, cc = idx & 31;
            float v = red[bf][0][s*32 + cc] + red[bf][1][s*32 + cc]
                    + red[bf][2][s*32 + cc] + red[bf][3][s*32 + cc];
            op[(size_t)(t0 + s)*1024 + cc] = v;
        }
    }
}

// ---------------------------------------------------------------------------
// RMSNorm * g_norm_w * swish(g) -> bf16 hi/lo for final GEMM
// ---------------------------------------------------------------------------
__global__ __launch_bounds__(128)
void epilogue_kernel(const float* __restrict__ g, const float* __restrict__ gnw)
{
    int m = blockIdx.x, wid = threadIdx.x >> 5, lane = threadIdx.x & 31;
    size_t off = (size_t)m*1024 + (size_t)wid*256 + (size_t)lane*8;

    float4 o0 = *(const float4*)(g_o + off);
    float4 o1 = *(const float4*)(g_o + off + 4);
    float ssq = o0.x*o0.x + o0.y*o0.y + o0.z*o0.z + o0.w*o0.w
              + o1.x*o1.x + o1.y*o1.y + o1.z*o1.z + o1.w*o1.w;
#pragma unroll
    for (int s = 16; s > 0; s >>= 1) ssq += __shfl_xor_sync(0xffffffffu, ssq, s);
    float rms = rsqrtf(ssq * (1.f/256.f) + 1e-5f);

    float4 gg0 = *(const float4*)(g + off);
    float4 gg1 = *(const float4*)(g + off + 4);
    const float* wv = gnw + lane*8;

    float r[8];
    r[0] = o0.x*rms*wv[0]*(gg0.x/(1.f+expf(-gg0.x)));
    r[1] = o0.y*rms*wv[1]*(gg0.y/(1.f+expf(-gg0.y)));
    r[2] = o0.z*rms*wv[2]*(gg0.z/(1.f+expf(-gg0.z)));
    r[3] = o0.w*rms*wv[3]*(gg0.w/(1.f+expf(-gg0.w)));
    r[4] = o1.x*rms*wv[4]*(gg1.x/(1.f+expf(-gg1.x)));
    r[5] = o1.y*rms*wv[5]*(gg1.y/(1.f+expf(-gg1.y)));
    r[6] = o1.z*rms*wv[6]*(gg1.z/(1.f+expf(-gg1.z)));
    r[7] = o1.w*rms*wv[7]*(gg1.w/(1.f+expf(-gg1.w)));

#pragma unroll
    for (int i = 0; i < 8; i += 2) {
        __nv_bfloat16 h0 = __float2bfloat16_rn(r[i]);
        __nv_bfloat16 h1 = __float2bfloat16_rn(r[i+1]);
        *(__nv_bfloat162*)(g_oh + off + i) = __halves2bfloat162(h0, h1);
        *(__nv_bfloat162*)(g_ol + off + i) = __halves2bfloat162(
            __float2bfloat16_rn(r[i]   - __bfloat162float(h0)),
            __float2bfloat16_rn(r[i+1] - __bfloat162float(h1)));
    }
}

// ---------------------------------------------------------------------------
extern "C" void kernel_launch(void* const* d_in, const int* in_sizes, int n_in,
                              void* d_out, int out_size)
{
    (void)in_sizes; (void)n_in; (void)out_size;
    const float* x     = (const float*)d_in[0];
    const float* Wq    = (const float*)d_in[1];
    const float* Wk    = (const float*)d_in[2];
    const float* Wv    = (const float*)d_in[3];
    const float* gk_w1 = (const float*)d_in[4];
    const float* gk_w2 = (const float*)d_in[5];
    const float* gk_b2 = (const float*)d_in[6];
    const float* Wg    = (const float*)d_in[7];
    const float* gnw   = (const float*)d_in[8];
    const float* Wo    = (const float*)d_in[9];
    float* out = (float*)d_out;

    __nv_bfloat16 *xh,*xl,*wah,*wal,*woh,*wol,*oh,*ol;
    float *pq,*pk,*pd,*pv,*pg;
    cudaGetSymbolAddress((void**)&xh, g_xh);   cudaGetSymbolAddress((void**)&xl, g_xl);
    cudaGetSymbolAddress((void**)&wah,g_wah);  cudaGetSymbolAddress((void**)&wal,g_wal);
    cudaGetSymbolAddress((void**)&woh,g_w_oh); cudaGetSymbolAddress((void**)&wol,g_w_ol);
    cudaGetSymbolAddress((void**)&oh, g_oh);   cudaGetSymbolAddress((void**)&ol, g_ol);
    cudaGetSymbolAddress((void**)&pq, g_q);    cudaGetSymbolAddress((void**)&pk, g_k);
    cudaGetSymbolAddress((void**)&pd, g_dcy);  cudaGetSymbolAddress((void**)&pv, g_v);
    cudaGetSymbolAddress((void**)&pg, g_g);

    cudaFuncSetAttribute(hgemm3<0>, cudaFuncAttributeMaxDynamicSharedMemorySize, SMEM4);
    cudaFuncSetAttribute(hgemm3<1>, cudaFuncAttributeMaxDynamicSharedMemorySize, SMEM4);

    // splits
    split_kernel<<<MM*1024/16/256, 256>>>(x, xh, xl, MM*1024);
    psplit_kernel<<<(1024*512/8 + 255)/256, 256>>>(Wq, 512,  0,    1024*512);
    psplit_kernel<<<(1024*512/8 + 255)/256, 256>>>(Wk, 512,  512,  1024*512);
    psplit_kernel<<<(1024*1024/8 + 255)/256, 256>>>(Wv, 1024, 1536, 1024*1024);
    psplit_kernel<<<(1024*1024/8 + 255)/256, 256>>>(Wg, 1024, 2560, 1024*1024);
    weff_psplit_kernel<<<(512*1024)/256, 256>>>(gk_w1, gk_w2);
    split_kernel<<<1024*1024/16/256, 256>>>(Wo, woh, wol, 1024*1024);

    dim3 blk(256);

    // GEMM1: packed q | k | decay | v | g   (N=3584, grid 28x256)
    hgemm3<1><<<dim3(28, MM/128), blk, SMEM4>>>(
        xh, xl, wah, wal, nullptr, 1024, NPACK, 1.f, gk_b2, pq, pk, pd, pv, pg);

    gla_rec_kernel<<<BB*4*8, 128>>>();
    epilogue_kernel<<<MM, 128>>>(pg, gnw);

    // out = o' @ Wo  (N=1024)
    hgemm3<0><<<dim3(8, MM/128), blk, SMEM4>>>(
        oh, ol, woh, wol, out, 1024, 1024, 1.f, nullptr,
        nullptr, nullptr, nullptr, nullptr, nullptr);
}

// round 11
// speedup vs baseline: 1.2850x; 1.2850x over previous
#include <cuda_runtime.h>
#include <cuda_fp16.h>
#include <cstdint>

// ---------------------------------------------------------------------------
// GLA block: B=8, T=4096, D=1024, H=4, Dk=128, Dv=256
// GEMMs: mma.sync fp16 2-term split: C = (Ah+Al)@Bh
//   activations hi/lo fp16 (exact to ~2^-22), weights single fp16 (2^-11).
//   Dropped term A@Bl -> per-GEMM rel err ~2.8e-4, final ~2.4e-4 (<1e-3).
// Topology: proven R9 (packed GEMM1 -> rec -> epilogue -> GEMM2).
// ---------------------------------------------------------------------------

#define BB   8
#define TT   4096
#define MM   (BB*TT)          // 32768
#define QSCALE 0.08838834764831845f
#define NPACK 3584            // packed q|k|decay|v|g

// ---------------- scratch (device globals; allocation-free) ----------------
__device__ __half g_xh[MM*1024], g_xl[MM*1024];
__device__ __half g_wa[1024*NPACK];          // packed fp16: Wq|Wk|Weff|Wv|Wg
__device__ __half g_wo[1024*1024];           // Wo fp16
__device__ float g_q[MM*512], g_k[MM*512], g_dcy[MM*512];
__device__ float g_v[MM*1024], g_g[MM*1024], g_o[MM*1024];
__device__ __half g_oh[MM*1024], g_ol[MM*1024];

__device__ __forceinline__ void cp16(uint32_t s, const void* g) {
    asm volatile("cp.async.cg.shared.global [%0], [%1], 16;" :: "r"(s), "l"(g));
}

// ---------------------------------------------------------------------------
// fp32 -> (fp16 hi, fp16 lo) split (activations); fp32 -> fp16 (weights)
// ---------------------------------------------------------------------------
__device__ __forceinline__ void hsplit8(const float* f, uint32_t* hp, uint32_t* lp)
{
#pragma unroll
    for (int j = 0; j < 4; j++) {
        __half h0 = __float2half_rn(f[2*j]);
        __half h1 = __float2half_rn(f[2*j+1]);
        __half2 hh = __halves2half2(h0, h1);
        __half2 ll = __halves2half2(
            __float2half_rn(f[2*j]   - __half2float(h0)),
            __float2half_rn(f[2*j+1] - __half2float(h1)));
        hp[j] = *(uint32_t*)&hh;
        lp[j] = *(uint32_t*)&ll;
    }
}

__global__ void split_kernel(const float* __restrict__ s,
                             __half* __restrict__ h,
                             __half* __restrict__ l, int n)
{
    int i = (blockIdx.x * blockDim.x + threadIdx.x) * 16;
    if (i >= n) return;
    float4 v0 = *(const float4*)(s + i);
    float4 v1 = *(const float4*)(s + i + 4);
    float4 v2 = *(const float4*)(s + i + 8);
    float4 v3 = *(const float4*)(s + i + 12);
    float f[16] = {v0.x, v0.y, v0.z, v0.w, v1.x, v1.y, v1.z, v1.w,
                   v2.x, v2.y, v2.z, v2.w, v3.x, v3.y, v3.z, v3.w};
    uint32_t hp[4], lp[4];
    hsplit8(f, hp, lp);
    *(uint4*)(h + i) = make_uint4(hp[0], hp[1], hp[2], hp[3]);
    *(uint4*)(l + i) = make_uint4(lp[0], lp[1], lp[2], lp[3]);
    hsplit8(f + 8, hp, lp);
    *(uint4*)(h + i + 8) = make_uint4(hp[0], hp[1], hp[2], hp[3]);
    *(uint4*)(l + i + 8) = make_uint4(lp[0], lp[1], lp[2], lp[3]);
}

// W[K,Nsrc] fp32 -> packed g_wa fp16 at column offset
__global__ void wsplit_kernel(const float* __restrict__ src, int Nsrc,
                              int coloff, int total)
{
    int i = (blockIdx.x * blockDim.x + threadIdx.x) * 8;
    if (i >= total) return;
    int k = i / Nsrc, n = i % Nsrc;
    float4 v0 = *(const float4*)(src + i);
    float4 v1 = *(const float4*)(src + i + 4);
    float f[8] = {v0.x, v0.y, v0.z, v0.w, v1.x, v1.y, v1.z, v1.w};
    uint32_t hp[4];
#pragma unroll
    for (int j = 0; j < 4; j++) {
        __half2 hh = __halves2half2(__float2half_rn(f[2*j]), __float2half_rn(f[2*j+1]));
        hp[j] = *(uint32_t*)&hh;
    }
    *(uint4*)(g_wa + (size_t)k * NPACK + coloff + n) = make_uint4(hp[0], hp[1], hp[2], hp[3]);
}

__global__ void wo_split_kernel(const float* __restrict__ src, int total)
{
    int i = (blockIdx.x * blockDim.x + threadIdx.x) * 8;
    if (i >= total) return;
    float4 v0 = *(const float4*)(src + i);
    float4 v1 = *(const float4*)(src + i + 4);
    float f[8] = {v0.x, v0.y, v0.z, v0.w, v1.x, v1.y, v1.z, v1.w};
    uint32_t hp[4];
#pragma unroll
    for (int j = 0; j < 4; j++) {
        __half2 hh = __halves2half2(__float2half_rn(f[2*j]), __float2half_rn(f[2*j+1]));
        hp[j] = *(uint32_t*)&hh;
    }
    *(uint4*)(g_wo + i) = make_uint4(hp[0], hp[1], hp[2], hp[3]);
}

// Weff = gk_w1 @ gk_w2 (1024x16 @ 16x512) -> packed cols [1024,1536), fp16
__global__ void weff_wsplit_kernel(const float* __restrict__ w1,
                                   const float* __restrict__ w2)
{
    int idx = blockIdx.x * blockDim.x + threadIdx.x;   // k*512 + n
    int kk = idx >> 9, n = idx & 511;
    float s = 0.f;
#pragma unroll
    for (int r = 0; r < 16; r++)
        s += w1[kk * 16 + r] * w2[r * 512 + n];
    g_wa[(size_t)kk * NPACK + 1024 + n] = __float2half_rn(s);
}

// ---------------------------------------------------------------------------
// fp16 2-term GEMM: C[M,N] = (Ah+Al)[M,K] @ B[K,N]
// BM=BN=128, BK=32, 3-stage cp.async (wait_group 1), warp tile 64x32.
// FUSED=1: packed epilogue routing (q|k|decay|v|g).
// ---------------------------------------------------------------------------
#define A_T 5120   // 128*40 elems per stage
#define B_T 4352   // 32*136 elems per stage
#define STG_B ((2*A_T + B_T) * 2)      // 29184 B per stage
#define SMEM3 (3 * STG_B)              // 87552 B

#define LDSM_X4(R0,R1,R2,R3,ADDR) \
    asm volatile("ldmatrix.sync.aligned.m8n8.x4.shared.b16 {%0,%1,%2,%3}, [%4];" \
        : "=r"(R0),"=r"(R1),"=r"(R2),"=r"(R3) : "r"(ADDR))
#define LDSM_X4T(R0,R1,R2,R3,ADDR) \
    asm volatile("ldmatrix.sync.aligned.m8n8.x4.trans.shared.b16 {%0,%1,%2,%3}, [%4];" \
        : "=r"(R0),"=r"(R1),"=r"(R2),"=r"(R3) : "r"(ADDR))
#define MMAH(D,A,B) \
    asm volatile("mma.sync.aligned.m16n8k16.row.col.f32.f16.f16.f32 " \
        "{%0,%1,%2,%3}, {%4,%5,%6,%7}, {%8,%9}, {%0,%1,%2,%3};" \
        : "+f"(D[0]),"+f"(D[1]),"+f"(D[2]),"+f"(D[3]) \
        : "r"(A[0]),"r"(A[1]),"r"(A[2]),"r"(A[3]),"r"(B[0]),"r"(B[1]))

template<int FUSED>
__global__ __launch_bounds__(256)
void hgemm2(const __half* __restrict__ Ah, const __half* __restrict__ Al,
            const __half* __restrict__ Bw,
            float* __restrict__ C, int K, int ldB, float scale,
            const float* __restrict__ bias,
            float* __restrict__ pq, float* __restrict__ pk, float* __restrict__ pd,
            float* __restrict__ pv, float* __restrict__ pgg)
{
    extern __shared__ __align__(16) __half sm[];

    const int tid = threadIdx.x;
    const int bn = blockIdx.x, bm = blockIdx.y;
    const int lane = tid & 31, wid = tid >> 5;
    const int wm = (wid & 1) * 64;
    const int wn = (wid >> 1) * 32;

    const int ar = tid >> 2, ac = (tid & 3) * 8;
    const int br = tid >> 4, bc = (tid & 15) * 8;

    const __half* gAh = Ah + (size_t)(bm*128 + ar) * K + ac;
    const __half* gAl = Al + (size_t)(bm*128 + ar) * K + ac;
    const __half* gB  = Bw + (size_t)br * ldB + bn*128 + bc;

    const uint32_t u0 = (uint32_t)__cvta_generic_to_shared(sm);
    const uint32_t a_st0 = (ar*40 + ac)*2, a_st1 = ((ar+64)*40 + ac)*2;
    const uint32_t b_st0 = (br*136 + bc)*2, b_st1 = ((br+16)*136 + bc)*2;

    float acc[4][4][4];
#pragma unroll
    for (int i = 0; i < 4; i++)
#pragma unroll
        for (int j = 0; j < 4; j++)
#pragma unroll
            for (int r = 0; r < 4; r++) acc[i][j][r] = 0.f;

    const int KT = K >> 5;

    auto load_stage = [&](int kt, int st) {
        const __half* pAh = gAh + kt*32;
        const __half* pAl = gAl + kt*32;
        const __half* pB  = gB  + (size_t)kt*32*ldB;
        uint32_t sb = u0 + (uint32_t)st * STG_B;
        cp16(sb + a_st0, pAh);
        cp16(sb + a_st1, pAh + (size_t)64*K);
        cp16(sb + A_T*2 + a_st0, pAl);
        cp16(sb + A_T*2 + a_st1, pAl + (size_t)64*K);
        cp16(sb + 4*A_T + b_st0, pB);
        cp16(sb + 4*A_T + b_st1, pB + (size_t)16*ldB);
        asm volatile("cp.async.commit_group;");
    };

    const int arow = wm + (lane & 15);
    const int acol = (lane >> 4) * 8;
    const int bkr  = (lane & 15);
    const int bcol = wn + ((lane >> 4) * 8);

    load_stage(0, 0);
    load_stage(1, 1);
    for (int kt = 0; kt < KT; kt++) {
        if (kt + 1 < KT)
            asm volatile("cp.async.wait_group 1;" ::: "memory");
        else
            asm volatile("cp.async.wait_group 0;" ::: "memory");
        __syncthreads();
        if (kt + 2 < KT) load_stage(kt + 2, (kt + 2) % 3);

        uint32_t sb  = u0 + (uint32_t)(kt % 3) * STG_B;
        uint32_t aBH = sb, aBL = sb + A_T*2;
        uint32_t bBH = sb + 4*A_T;
#pragma unroll
        for (int ks = 0; ks < 2; ks++) {
            uint32_t ah[4][4], al[4][4], bh[4][2];
#pragma unroll
            for (int mi = 0; mi < 4; mi++) {
                uint32_t off = ((arow + mi*16)*40 + ks*16 + acol) * 2;
                LDSM_X4(ah[mi][0], ah[mi][1], ah[mi][2], ah[mi][3], aBH + off);
                LDSM_X4(al[mi][0], al[mi][1], al[mi][2], al[mi][3], aBL + off);
            }
#pragma unroll
            for (int p = 0; p < 2; p++) {
                uint32_t off = ((ks*16 + bkr)*136 + bcol + p*16) * 2;
                LDSM_X4T(bh[2*p][0], bh[2*p][1], bh[2*p+1][0], bh[2*p+1][1], bBH + off);
            }
#pragma unroll
            for (int mi = 0; mi < 4; mi++)
#pragma unroll
                for (int ni = 0; ni < 4; ni++) MMAH(acc[mi][ni], ah[mi], bh[ni]);
#pragma unroll
            for (int mi = 0; mi < 4; mi++)
#pragma unroll
                for (int ni = 0; ni < 4; ni++) MMAH(acc[mi][ni], al[mi], bh[ni]);
        }
    }

    float* dst; int ldo, coff, kind; float sc = scale;
    if (FUSED) {
        if      (bn < 4)  { dst = pq;  ldo = 512;  coff = 0;    kind = 0; sc = QSCALE; }
        else if (bn < 8)  { dst = pk;  ldo = 512;  coff = 512;  kind = 1; }
        else if (bn < 12) { dst = pd;  ldo = 512;  coff = 1024; kind = 2; }
        else if (bn < 20) { dst = pv;  ldo = 1024; coff = 1536; kind = 1; }
        else              { dst = pgg; ldo = 1024; coff = 2560; kind = 1; }
    } else {
        dst = C; ldo = ldB; coff = 0; kind = 0;
    }

#pragma unroll
    for (int mi = 0; mi < 4; mi++) {
        int r0 = bm*128 + wm + mi*16 + (lane >> 2);
#pragma unroll
        for (int ni = 0; ni < 4; ni++) {
            int gc = bn*128 + wn + ni*8 + (lane & 3)*2;
            int c = gc - coff;
            float o0 = acc[mi][ni][0], o1 = acc[mi][ni][1];
            float o2 = acc[mi][ni][2], o3 = acc[mi][ni][3];
            if (kind == 0) {
                o0 *= sc; o1 *= sc; o2 *= sc; o3 *= sc;
            } else if (kind == 2) {
                float b0 = bias[c], b1 = bias[c + 1];
                float z, sp;
                z = o0 + b0; sp = fmaxf(-z,0.f) + log1pf(expf(-fabsf(z))); o0 = expf(-sp*0.0625f);
                z = o1 + b1; sp = fmaxf(-z,0.f) + log1pf(expf(-fabsf(z))); o1 = expf(-sp*0.0625f);
                z = o2 + b0; sp = fmaxf(-z,0.f) + log1pf(expf(-fabsf(z))); o2 = expf(-sp*0.0625f);
                z = o3 + b1; sp = fmaxf(-z,0.f) + log1pf(expf(-fabsf(z))); o3 = expf(-sp*0.0625f);
            }
            *(float2*)(dst + (size_t)r0 * ldo + c)       = make_float2(o0, o1);
            *(float2*)(dst + (size_t)(r0 + 8) * ldo + c) = make_float2(o2, o3);
        }
    }
}

// ---------------------------------------------------------------------------
// GLA recurrence (R9 proven version, unchanged)
// ---------------------------------------------------------------------------
#define RC 8
#define NCH (TT/RC)

__global__ __launch_bounds__(128)
void gla_rec_kernel()
{
    __shared__ __align__(16) float sq[2][RC*128], sk[2][RC*128], sd[2][RC*128];
    __shared__ __align__(16) float sv[2][RC*32];
    __shared__ float red[2][4][RC*32];

    int bid = blockIdx.x;
    int dvt = bid & 7, h = (bid >> 3) & 3, b = bid >> 5;
    int tid = threadIdx.x, c = tid & 31, w = tid >> 5;

    size_t base_qk = ((size_t)b*TT)*512 + (size_t)h*128;
    size_t base_v  = ((size_t)b*TT)*1024 + (size_t)h*256 + (size_t)dvt*32;
    const float* qp = g_q + base_qk;
    const float* kp = g_k + base_qk;
    const float* dp = g_dcy + base_qk;
    const float* vp = g_v + base_v;
    float* op = g_o + base_v;

    const uint32_t uq = (uint32_t)__cvta_generic_to_shared(&sq[0][0]);
    const uint32_t uk = (uint32_t)__cvta_generic_to_shared(&sk[0][0]);
    const uint32_t ud = (uint32_t)__cvta_generic_to_shared(&sd[0][0]);
    const uint32_t uv = (uint32_t)__cvta_generic_to_shared(&sv[0][0]);

    auto load = [&](int t0, int bf) {
        uint32_t bo = (uint32_t)bf * (RC*128*4);
#pragma unroll
        for (int j = 0; j < 2; j++) {
            int idx = tid + j*128;
            int s = idx >> 5, seg = idx & 31;
            uint32_t so = (uint32_t)((s*128 + seg*4) * 4);
            size_t go = (size_t)(t0 + s)*512 + seg*4;
            cp16(uq + bo + so, qp + go);
            cp16(uk + bo + so, kp + go);
            cp16(ud + bo + so, dp + go);
        }
        if (tid < 64) {
            int s = tid >> 3, seg = tid & 7;
            cp16(uv + (uint32_t)bf*(RC*32*4) + (uint32_t)((s*32 + seg*4)*4),
                 vp + (size_t)(t0 + s)*1024 + seg*4);
        }
        asm volatile("cp.async.commit_group;" ::: "memory");
    };

    unsigned long long S2[16];
#pragma unroll
    for (int i = 0; i < 16; i++) S2[i] = 0ull;

    load(0, 0);
    for (int ci = 0; ci < NCH; ci++) {
        asm volatile("cp.async.wait_group 0;" ::: "memory");
        __syncthreads();
        if (ci + 1 < NCH) load((ci + 1)*RC, (ci + 1) & 1);

        int bf = ci & 1, t0 = ci*RC;
#pragma unroll 2
        for (int s = 0; s < RC; s++) {
            const ulonglong2* q4 = (const ulonglong2*)(&sq[bf][s*128 + w*32]);
            const ulonglong2* k4 = (const ulonglong2*)(&sk[bf][s*128 + w*32]);
            const ulonglong2* d4 = (const ulonglong2*)(&sd[bf][s*128 + w*32]);
            float vj = sv[bf][s*32 + c];
            unsigned long long vv;
            asm("mov.b64 %0, {%1, %1};" : "=l"(vv) : "f"(vj));
            unsigned long long ac[4] = {0ull, 0ull, 0ull, 0ull};
#pragma unroll
            for (int i = 0; i < 8; i++) {
                ulonglong2 qv = q4[i], kv = k4[i], dv = d4[i];
                unsigned long long t;
                asm("mul.rn.f32x2 %0, %1, %2;" : "=l"(t) : "l"(kv.x), "l"(vv));
                asm("fma.rn.f32x2 %0, %1, %2, %3;" : "=l"(S2[2*i])   : "l"(dv.x), "l"(S2[2*i]),   "l"(t));
                asm("fma.rn.f32x2 %0, %1, %2, %3;" : "=l"(ac[(2*i)&3])   : "l"(qv.x), "l"(S2[2*i]),   "l"(ac[(2*i)&3]));
                asm("mul.rn.f32x2 %0, %1, %2;" : "=l"(t) : "l"(kv.y), "l"(vv));
                asm("fma.rn.f32x2 %0, %1, %2, %3;" : "=l"(S2[2*i+1]) : "l"(dv.y), "l"(S2[2*i+1]), "l"(t));
                asm("fma.rn.f32x2 %0, %1, %2, %3;" : "=l"(ac[(2*i+1)&3]) : "l"(qv.y), "l"(S2[2*i+1]), "l"(ac[(2*i+1)&3]));
            }
            float p = 0.f;
#pragma unroll
            for (int j = 0; j < 4; j++) {
                float x0, x1;
                asm("mov.b64 {%0, %1}, %2;" : "=f"(x0), "=f"(x1) : "l"(ac[j]));
                p += x0 + x1;
            }
            red[bf][w][s*32 + c] = p;
        }
        __syncthreads();
#pragma unroll
        for (int j = 0; j < 2; j++) {
            int idx = tid + j*128;
            int s = idx >> 5, cc = idx & 31;
            float v = red[bf][0][s*32 + cc] + red[bf][1][s*32 + cc]
                    + red[bf][2][s*32 + cc] + red[bf][3][s*32 + cc];
            op[(size_t)(t0 + s)*1024 + cc] = v;
        }
    }
}

// ---------------------------------------------------------------------------
// RMSNorm * g_norm_w * swish(g) -> fp16 hi/lo for final GEMM
// ---------------------------------------------------------------------------
__global__ __launch_bounds__(128)
void epilogue_kernel(const float* __restrict__ g, const float* __restrict__ gnw)
{
    int m = blockIdx.x, wid = threadIdx.x >> 5, lane = threadIdx.x & 31;
    size_t off = (size_t)m*1024 + (size_t)wid*256 + (size_t)lane*8;

    float4 o0 = *(const float4*)(g_o + off);
    float4 o1 = *(const float4*)(g_o + off + 4);
    float ssq = o0.x*o0.x + o0.y*o0.y + o0.z*o0.z + o0.w*o0.w
              + o1.x*o1.x + o1.y*o1.y + o1.z*o1.z + o1.w*o1.w;
#pragma unroll
    for (int s = 16; s > 0; s >>= 1) ssq += __shfl_xor_sync(0xffffffffu, ssq, s);
    float rms = rsqrtf(ssq * (1.f/256.f) + 1e-5f);

    float4 gg0 = *(const float4*)(g + off);
    float4 gg1 = *(const float4*)(g + off + 4);
    const float* wv = gnw + lane*8;

    float r[8];
    r[0] = o0.x*rms*wv[0]*(gg0.x/(1.f+expf(-gg0.x)));
    r[1] = o0.y*rms*wv[1]*(gg0.y/(1.f+expf(-gg0.y)));
    r[2] = o0.z*rms*wv[2]*(gg0.z/(1.f+expf(-gg0.z)));
    r[3] = o0.w*rms*wv[3]*(gg0.w/(1.f+expf(-gg0.w)));
    r[4] = o1.x*rms*wv[4]*(gg1.x/(1.f+expf(-gg1.x)));
    r[5] = o1.y*rms*wv[5]*(gg1.y/(1.f+expf(-gg1.y)));
    r[6] = o1.z*rms*wv[6]*(gg1.z/(1.f+expf(-gg1.z)));
    r[7] = o1.w*rms*wv[7]*(gg1.w/(1.f+expf(-gg1.w)));

#pragma unroll
    for (int i = 0; i < 8; i += 2) {
        __half h0 = __float2half_rn(r[i]);
        __half h1 = __float2half_rn(r[i+1]);
        *(__half2*)(g_oh + off + i) = __halves2half2(h0, h1);
        *(__half2*)(g_ol + off + i) = __halves2half2(
            __float2half_rn(r[i]   - __half2float(h0)),
            __float2half_rn(r[i+1] - __half2float(h1)));
    }
}

// ---------------------------------------------------------------------------
extern "C" void kernel_launch(void* const* d_in, const int* in_sizes, int n_in,
                              void* d_out, int out_size)
{
    (void)in_sizes; (void)n_in; (void)out_size;
    const float* x     = (const float*)d_in[0];
    const float* Wq    = (const float*)d_in[1];
    const float* Wk    = (const float*)d_in[2];
    const float* Wv    = (const float*)d_in[3];
    const float* gk_w1 = (const float*)d_in[4];
    const float* gk_w2 = (const float*)d_in[5];
    const float* gk_b2 = (const float*)d_in[6];
    const float* Wg    = (const float*)d_in[7];
    const float* gnw   = (const float*)d_in[8];
    const float* Wo    = (const float*)d_in[9];
    float* out = (float*)d_out;

    __half *xh,*xl,*wa,*wo,*oh,*ol;
    float *pq,*pk,*pd,*pv,*pg;
    cudaGetSymbolAddress((void**)&xh, g_xh);  cudaGetSymbolAddress((void**)&xl, g_xl);
    cudaGetSymbolAddress((void**)&wa, g_wa);  cudaGetSymbolAddress((void**)&wo, g_wo);
    cudaGetSymbolAddress((void**)&oh, g_oh);  cudaGetSymbolAddress((void**)&ol, g_ol);
    cudaGetSymbolAddress((void**)&pq, g_q);   cudaGetSymbolAddress((void**)&pk, g_k);
    cudaGetSymbolAddress((void**)&pd, g_dcy); cudaGetSymbolAddress((void**)&pv, g_v);
    cudaGetSymbolAddress((void**)&pg, g_g);

    cudaFuncSetAttribute(hgemm2<0>, cudaFuncAttributeMaxDynamicSharedMemorySize, SMEM3);
    cudaFuncSetAttribute(hgemm2<1>, cudaFuncAttributeMaxDynamicSharedMemorySize, SMEM3);

    // splits
    split_kernel<<<MM*1024/16/256, 256>>>(x, xh, xl, MM*1024);
    wsplit_kernel<<<(1024*512/8 + 255)/256, 256>>>(Wq, 512,  0,    1024*512);
    wsplit_kernel<<<(1024*512/8 + 255)/256, 256>>>(Wk, 512,  512,  1024*512);
    wsplit_kernel<<<(1024*1024/8 + 255)/256, 256>>>(Wv, 1024, 1536, 1024*1024);
    wsplit_kernel<<<(1024*1024/8 + 255)/256, 256>>>(Wg, 1024, 2560, 1024*1024);
    weff_wsplit_kernel<<<(512*1024)/256, 256>>>(gk_w1, gk_w2);
    wo_split_kernel<<<(1024*1024/8 + 255)/256, 256>>>(Wo, 1024*1024);

    dim3 blk(256);

    // GEMM1: packed q | k | decay | v | g   (N=3584, grid 28x256)
    hgemm2<1><<<dim3(28, MM/128), blk, SMEM3>>>(
        xh, xl, wa, nullptr, 1024, NPACK, 1.f, gk_b2, pq, pk, pd, pv, pg);

    gla_rec_kernel<<<BB*4*8, 128>>>();
    epilogue_kernel<<<MM, 128>>>(pg, gnw);

    // out = o' @ Wo  (N=1024)
    hgemm2<0><<<dim3(8, MM/128), blk, SMEM3>>>(
        oh, ol, wo, out, 1024, 1024, 1.f, nullptr,
        nullptr, nullptr, nullptr, nullptr, nullptr);
}

// round 12
// speedup vs baseline: 1.5974x; 1.2431x over previous
#include <cuda_runtime.h>
#include <cuda_fp16.h>
#include <cstdint>

// ---------------------------------------------------------------------------
// GLA block: B=8, T=4096, D=1024, H=4, Dk=128, Dv=256
// GEMMs: mma.sync fp16 split, per-path precision:
//   q,k: 2-term (Ah+Al)@B ; decay/v/g and GEMM2: 1-term Ah@B
//   (decay damped 16x by gate normalizer; v/g/out each add ~2.4e-4 in quadrature)
// Topology: proven R9/R11 (packed GEMM1 -> rec -> epilogue -> GEMM2).
// ---------------------------------------------------------------------------

#define BB   8
#define TT   4096
#define MM   (BB*TT)          // 32768
#define QSCALE 0.08838834764831845f
#define NPACK 3584            // packed q|k|decay|v|g

// ---------------- scratch (device globals; allocation-free) ----------------
__device__ __half g_xh[MM*1024], g_xl[MM*1024];
__device__ __half g_wa[1024*NPACK];          // packed fp16: Wq|Wk|Weff|Wv|Wg
__device__ __half g_wo[1024*1024];           // Wo fp16
__device__ float g_q[MM*512], g_k[MM*512], g_dcy[MM*512];
__device__ float g_v[MM*1024], g_g[MM*1024], g_o[MM*1024];
__device__ __half g_oh[MM*1024];

__device__ __forceinline__ void cp16(uint32_t s, const void* g) {
    asm volatile("cp.async.cg.shared.global [%0], [%1], 16;" :: "r"(s), "l"(g));
}

// ---------------------------------------------------------------------------
// fp32 -> (fp16 hi, fp16 lo) split (activations); fp32 -> fp16 (weights)
// ---------------------------------------------------------------------------
__device__ __forceinline__ void hsplit8(const float* f, uint32_t* hp, uint32_t* lp)
{
#pragma unroll
    for (int j = 0; j < 4; j++) {
        __half h0 = __float2half_rn(f[2*j]);
        __half h1 = __float2half_rn(f[2*j+1]);
        __half2 hh = __halves2half2(h0, h1);
        __half2 ll = __halves2half2(
            __float2half_rn(f[2*j]   - __half2float(h0)),
            __float2half_rn(f[2*j+1] - __half2float(h1)));
        hp[j] = *(uint32_t*)&hh;
        lp[j] = *(uint32_t*)&ll;
    }
}

__global__ void split_kernel(const float* __restrict__ s,
                             __half* __restrict__ h,
                             __half* __restrict__ l, int n)
{
    int i = (blockIdx.x * blockDim.x + threadIdx.x) * 16;
    if (i >= n) return;
    float4 v0 = *(const float4*)(s + i);
    float4 v1 = *(const float4*)(s + i + 4);
    float4 v2 = *(const float4*)(s + i + 8);
    float4 v3 = *(const float4*)(s + i + 12);
    float f[16] = {v0.x, v0.y, v0.z, v0.w, v1.x, v1.y, v1.z, v1.w,
                   v2.x, v2.y, v2.z, v2.w, v3.x, v3.y, v3.z, v3.w};
    uint32_t hp[4], lp[4];
    hsplit8(f, hp, lp);
    *(uint4*)(h + i) = make_uint4(hp[0], hp[1], hp[2], hp[3]);
    *(uint4*)(l + i) = make_uint4(lp[0], lp[1], lp[2], lp[3]);
    hsplit8(f + 8, hp, lp);
    *(uint4*)(h + i + 8) = make_uint4(hp[0], hp[1], hp[2], hp[3]);
    *(uint4*)(l + i + 8) = make_uint4(lp[0], lp[1], lp[2], lp[3]);
}

// W[K,Nsrc] fp32 -> packed g_wa fp16 at column offset
__global__ void wsplit_kernel(const float* __restrict__ src, int Nsrc,
                              int coloff, int total)
{
    int i = (blockIdx.x * blockDim.x + threadIdx.x) * 8;
    if (i >= total) return;
    int k = i / Nsrc, n = i % Nsrc;
    float4 v0 = *(const float4*)(src + i);
    float4 v1 = *(const float4*)(src + i + 4);
    float f[8] = {v0.x, v0.y, v0.z, v0.w, v1.x, v1.y, v1.z, v1.w};
    uint32_t hp[4];
#pragma unroll
    for (int j = 0; j < 4; j++) {
        __half2 hh = __halves2half2(__float2half_rn(f[2*j]), __float2half_rn(f[2*j+1]));
        hp[j] = *(uint32_t*)&hh;
    }
    *(uint4*)(g_wa + (size_t)k * NPACK + coloff + n) = make_uint4(hp[0], hp[1], hp[2], hp[3]);
}

__global__ void wo_split_kernel(const float* __restrict__ src, int total)
{
    int i = (blockIdx.x * blockDim.x + threadIdx.x) * 8;
    if (i >= total) return;
    float4 v0 = *(const float4*)(src + i);
    float4 v1 = *(const float4*)(src + i + 4);
    float f[8] = {v0.x, v0.y, v0.z, v0.w, v1.x, v1.y, v1.z, v1.w};
    uint32_t hp[4];
#pragma unroll
    for (int j = 0; j < 4; j++) {
        __half2 hh = __halves2half2(__float2half_rn(f[2*j]), __float2half_rn(f[2*j+1]));
        hp[j] = *(uint32_t*)&hh;
    }
    *(uint4*)(g_wo + i) = make_uint4(hp[0], hp[1], hp[2], hp[3]);
}

// Weff = gk_w1 @ gk_w2 (1024x16 @ 16x512) -> packed cols [1024,1536), fp16
__global__ void weff_wsplit_kernel(const float* __restrict__ w1,
                                   const float* __restrict__ w2)
{
    int idx = blockIdx.x * blockDim.x + threadIdx.x;   // k*512 + n
    int kk = idx >> 9, n = idx & 511;
    float s = 0.f;
#pragma unroll
    for (int r = 0; r < 16; r++)
        s += w1[kk * 16 + r] * w2[r * 512 + n];
    g_wa[(size_t)kk * NPACK + 1024 + n] = __float2half_rn(s);
}

// ---------------------------------------------------------------------------
// fp16 GEMM: C[M,N] = (Ah [+ Al])@B. TERMS=2 enables the Al term; in FUSED
// mode the Al term is applied only for q,k tiles (bn<8).
// BM=BN=128, BK=32, 3-stage cp.async (wait_group 1), warp tile 64x32.
// ---------------------------------------------------------------------------
#define A_T 5120   // 128*40 elems per stage
#define B_T 4352   // 32*136 elems per stage
#define STG_B ((2*A_T + B_T) * 2)      // 29184 B per stage
#define SMEM3 (3 * STG_B)              // 87552 B

#define LDSM_X4(R0,R1,R2,R3,ADDR) \
    asm volatile("ldmatrix.sync.aligned.m8n8.x4.shared.b16 {%0,%1,%2,%3}, [%4];" \
        : "=r"(R0),"=r"(R1),"=r"(R2),"=r"(R3) : "r"(ADDR))
#define LDSM_X4T(R0,R1,R2,R3,ADDR) \
    asm volatile("ldmatrix.sync.aligned.m8n8.x4.trans.shared.b16 {%0,%1,%2,%3}, [%4];" \
        : "=r"(R0),"=r"(R1),"=r"(R2),"=r"(R3) : "r"(ADDR))
#define MMAH(D,A,B) \
    asm volatile("mma.sync.aligned.m16n8k16.row.col.f32.f16.f16.f32 " \
        "{%0,%1,%2,%3}, {%4,%5,%6,%7}, {%8,%9}, {%0,%1,%2,%3};" \
        : "+f"(D[0]),"+f"(D[1]),"+f"(D[2]),"+f"(D[3]) \
        : "r"(A[0]),"r"(A[1]),"r"(A[2]),"r"(A[3]),"r"(B[0]),"r"(B[1]))

template<int FUSED, int TERMS>
__global__ __launch_bounds__(256)
void hgemm2(const __half* __restrict__ Ah, const __half* __restrict__ Al,
            const __half* __restrict__ Bw,
            float* __restrict__ C, int K, int ldB, float scale,
            const float* __restrict__ bias,
            float* __restrict__ pq, float* __restrict__ pk, float* __restrict__ pd,
            float* __restrict__ pv, float* __restrict__ pgg)
{
    extern __shared__ __align__(16) __half sm[];

    const int tid = threadIdx.x;
    const int bn = blockIdx.x, bm = blockIdx.y;
    const int lane = tid & 31, wid = tid >> 5;
    const int wm = (wid & 1) * 64;
    const int wn = (wid >> 1) * 32;

    // q,k tiles (bn<8 in FUSED) get the Al correction term; others skip it.
    const bool use_al = (TERMS == 2) && (!FUSED || bn < 8);

    const int ar = tid >> 2, ac = (tid & 3) * 8;
    const int br = tid >> 4, bc = (tid & 15) * 8;

    const __half* gAh = Ah + (size_t)(bm*128 + ar) * K + ac;
    const __half* gAl = Al + (size_t)(bm*128 + ar) * K + ac;
    const __half* gB  = Bw + (size_t)br * ldB + bn*128 + bc;

    const uint32_t u0 = (uint32_t)__cvta_generic_to_shared(sm);
    const uint32_t a_st0 = (ar*40 + ac)*2, a_st1 = ((ar+64)*40 + ac)*2;
    const uint32_t b_st0 = (br*136 + bc)*2, b_st1 = ((br+16)*136 + bc)*2;

    float acc[4][4][4];
#pragma unroll
    for (int i = 0; i < 4; i++)
#pragma unroll
        for (int j = 0; j < 4; j++)
#pragma unroll
            for (int r = 0; r < 4; r++) acc[i][j][r] = 0.f;

    const int KT = K >> 5;

    auto load_stage = [&](int kt, int st) {
        const __half* pAh = gAh + kt*32;
        const __half* pAl = gAl + kt*32;
        const __half* pB  = gB  + (size_t)kt*32*ldB;
        uint32_t sb = u0 + (uint32_t)st * STG_B;
        cp16(sb + a_st0, pAh);
        cp16(sb + a_st1, pAh + (size_t)64*K);
        if (use_al) {
            cp16(sb + A_T*2 + a_st0, pAl);
            cp16(sb + A_T*2 + a_st1, pAl + (size_t)64*K);
        }
        cp16(sb + 4*A_T + b_st0, pB);
        cp16(sb + 4*A_T + b_st1, pB + (size_t)16*ldB);
        asm volatile("cp.async.commit_group;");
    };

    const int arow = wm + (lane & 15);
    const int acol = (lane >> 4) * 8;
    const int bkr  = (lane & 15);
    const int bcol = wn + ((lane >> 4) * 8);

    load_stage(0, 0);
    load_stage(1, 1);
    for (int kt = 0; kt < KT; kt++) {
        if (kt + 1 < KT)
            asm volatile("cp.async.wait_group 1;" ::: "memory");
        else
            asm volatile("cp.async.wait_group 0;" ::: "memory");
        __syncthreads();
        if (kt + 2 < KT) load_stage(kt + 2, (kt + 2) % 3);

        uint32_t sb  = u0 + (uint32_t)(kt % 3) * STG_B;
        uint32_t aBH = sb, aBL = sb + A_T*2;
        uint32_t bBH = sb + 4*A_T;
#pragma unroll
        for (int ks = 0; ks < 2; ks++) {
            uint32_t ah[4][4], al[4][4], bh[4][2];
#pragma unroll
            for (int mi = 0; mi < 4; mi++) {
                uint32_t off = ((arow + mi*16)*40 + ks*16 + acol) * 2;
                LDSM_X4(ah[mi][0], ah[mi][1], ah[mi][2], ah[mi][3], aBH + off);
                if (use_al)
                    LDSM_X4(al[mi][0], al[mi][1], al[mi][2], al[mi][3], aBL + off);
            }
#pragma unroll
            for (int p = 0; p < 2; p++) {
                uint32_t off = ((ks*16 + bkr)*136 + bcol + p*16) * 2;
                LDSM_X4T(bh[2*p][0], bh[2*p][1], bh[2*p+1][0], bh[2*p+1][1], bBH + off);
            }
#pragma unroll
            for (int mi = 0; mi < 4; mi++)
#pragma unroll
                for (int ni = 0; ni < 4; ni++) MMAH(acc[mi][ni], ah[mi], bh[ni]);
            if (use_al) {
#pragma unroll
                for (int mi = 0; mi < 4; mi++)
#pragma unroll
                    for (int ni = 0; ni < 4; ni++) MMAH(acc[mi][ni], al[mi], bh[ni]);
            }
        }
    }

    float* dst; int ldo, coff, kind; float sc = scale;
    if (FUSED) {
        if      (bn < 4)  { dst = pq;  ldo = 512;  coff = 0;    kind = 0; sc = QSCALE; }
        else if (bn < 8)  { dst = pk;  ldo = 512;  coff = 512;  kind = 1; }
        else if (bn < 12) { dst = pd;  ldo = 512;  coff = 1024; kind = 2; }
        else if (bn < 20) { dst = pv;  ldo = 1024; coff = 1536; kind = 1; }
        else              { dst = pgg; ldo = 1024; coff = 2560; kind = 1; }
    } else {
        dst = C; ldo = ldB; coff = 0; kind = 0;
    }

#pragma unroll
    for (int mi = 0; mi < 4; mi++) {
        int r0 = bm*128 + wm + mi*16 + (lane >> 2);
#pragma unroll
        for (int ni = 0; ni < 4; ni++) {
            int gc = bn*128 + wn + ni*8 + (lane & 3)*2;
            int c = gc - coff;
            float o0 = acc[mi][ni][0], o1 = acc[mi][ni][1];
            float o2 = acc[mi][ni][2], o3 = acc[mi][ni][3];
            if (kind == 0) {
                o0 *= sc; o1 *= sc; o2 *= sc; o3 *= sc;
            } else if (kind == 2) {
                float b0 = bias[c], b1 = bias[c + 1];
                float z, sp;
                z = o0 + b0; sp = fmaxf(-z,0.f) + log1pf(expf(-fabsf(z))); o0 = expf(-sp*0.0625f);
                z = o1 + b1; sp = fmaxf(-z,0.f) + log1pf(expf(-fabsf(z))); o1 = expf(-sp*0.0625f);
                z = o2 + b0; sp = fmaxf(-z,0.f) + log1pf(expf(-fabsf(z))); o2 = expf(-sp*0.0625f);
                z = o3 + b1; sp = fmaxf(-z,0.f) + log1pf(expf(-fabsf(z))); o3 = expf(-sp*0.0625f);
            }
            *(float2*)(dst + (size_t)r0 * ldo + c)       = make_float2(o0, o1);
            *(float2*)(dst + (size_t)(r0 + 8) * ldo + c) = make_float2(o2, o3);
        }
    }
}

// ---------------------------------------------------------------------------
// GLA recurrence (R9/R11 proven version, unchanged)
// ---------------------------------------------------------------------------
#define RC 8
#define NCH (TT/RC)

__global__ __launch_bounds__(128)
void gla_rec_kernel()
{
    __shared__ __align__(16) float sq[2][RC*128], sk[2][RC*128], sd[2][RC*128];
    __shared__ __align__(16) float sv[2][RC*32];
    __shared__ float red[2][4][RC*32];

    int bid = blockIdx.x;
    int dvt = bid & 7, h = (bid >> 3) & 3, b = bid >> 5;
    int tid = threadIdx.x, c = tid & 31, w = tid >> 5;

    size_t base_qk = ((size_t)b*TT)*512 + (size_t)h*128;
    size_t base_v  = ((size_t)b*TT)*1024 + (size_t)h*256 + (size_t)dvt*32;
    const float* qp = g_q + base_qk;
    const float* kp = g_k + base_qk;
    const float* dp = g_dcy + base_qk;
    const float* vp = g_v + base_v;
    float* op = g_o + base_v;

    const uint32_t uq = (uint32_t)__cvta_generic_to_shared(&sq[0][0]);
    const uint32_t uk = (uint32_t)__cvta_generic_to_shared(&sk[0][0]);
    const uint32_t ud = (uint32_t)__cvta_generic_to_shared(&sd[0][0]);
    const uint32_t uv = (uint32_t)__cvta_generic_to_shared(&sv[0][0]);

    auto load = [&](int t0, int bf) {
        uint32_t bo = (uint32_t)bf * (RC*128*4);
#pragma unroll
        for (int j = 0; j < 2; j++) {
            int idx = tid + j*128;
            int s = idx >> 5, seg = idx & 31;
            uint32_t so = (uint32_t)((s*128 + seg*4) * 4);
            size_t go = (size_t)(t0 + s)*512 + seg*4;
            cp16(uq + bo + so, qp + go);
            cp16(uk + bo + so, kp + go);
            cp16(ud + bo + so, dp + go);
        }
        if (tid < 64) {
            int s = tid >> 3, seg = tid & 7;
            cp16(uv + (uint32_t)bf*(RC*32*4) + (uint32_t)((s*32 + seg*4)*4),
                 vp + (size_t)(t0 + s)*1024 + seg*4);
        }
        asm volatile("cp.async.commit_group;" ::: "memory");
    };

    unsigned long long S2[16];
#pragma unroll
    for (int i = 0; i < 16; i++) S2[i] = 0ull;

    load(0, 0);
    for (int ci = 0; ci < NCH; ci++) {
        asm volatile("cp.async.wait_group 0;" ::: "memory");
        __syncthreads();
        if (ci + 1 < NCH) load((ci + 1)*RC, (ci + 1) & 1);

        int bf = ci & 1, t0 = ci*RC;
#pragma unroll 2
        for (int s = 0; s < RC; s++) {
            const ulonglong2* q4 = (const ulonglong2*)(&sq[bf][s*128 + w*32]);
            const ulonglong2* k4 = (const ulonglong2*)(&sk[bf][s*128 + w*32]);
            const ulonglong2* d4 = (const ulonglong2*)(&sd[bf][s*128 + w*32]);
            float vj = sv[bf][s*32 + c];
            unsigned long long vv;
            asm("mov.b64 %0, {%1, %1};" : "=l"(vv) : "f"(vj));
            unsigned long long ac[4] = {0ull, 0ull, 0ull, 0ull};
#pragma unroll
            for (int i = 0; i < 8; i++) {
                ulonglong2 qv = q4[i], kv = k4[i], dv = d4[i];
                unsigned long long t;
                asm("mul.rn.f32x2 %0, %1, %2;" : "=l"(t) : "l"(kv.x), "l"(vv));
                asm("fma.rn.f32x2 %0, %1, %2, %3;" : "=l"(S2[2*i])   : "l"(dv.x), "l"(S2[2*i]),   "l"(t));
                asm("fma.rn.f32x2 %0, %1, %2, %3;" : "=l"(ac[(2*i)&3])   : "l"(qv.x), "l"(S2[2*i]),   "l"(ac[(2*i)&3]));
                asm("mul.rn.f32x2 %0, %1, %2;" : "=l"(t) : "l"(kv.y), "l"(vv));
                asm("fma.rn.f32x2 %0, %1, %2, %3;" : "=l"(S2[2*i+1]) : "l"(dv.y), "l"(S2[2*i+1]), "l"(t));
                asm("fma.rn.f32x2 %0, %1, %2, %3;" : "=l"(ac[(2*i+1)&3]) : "l"(qv.y), "l"(S2[2*i+1]), "l"(ac[(2*i+1)&3]));
            }
            float p = 0.f;
#pragma unroll
            for (int j = 0; j < 4; j++) {
                float x0, x1;
                asm("mov.b64 {%0, %1}, %2;" : "=f"(x0), "=f"(x1) : "l"(ac[j]));
                p += x0 + x1;
            }
            red[bf][w][s*32 + c] = p;
        }
        __syncthreads();
#pragma unroll
        for (int j = 0; j < 2; j++) {
            int idx = tid + j*128;
            int s = idx >> 5, cc = idx & 31;
            float v = red[bf][0][s*32 + cc] + red[bf][1][s*32 + cc]
                    + red[bf][2][s*32 + cc] + red[bf][3][s*32 + cc];
            op[(size_t)(t0 + s)*1024 + cc] = v;
        }
    }
}

// ---------------------------------------------------------------------------
// RMSNorm * g_norm_w * swish(g) -> fp16 (hi only; GEMM2 is 1-term)
// ---------------------------------------------------------------------------
__global__ __launch_bounds__(128)
void epilogue_kernel(const float* __restrict__ g, const float* __restrict__ gnw)
{
    int m = blockIdx.x, wid = threadIdx.x >> 5, lane = threadIdx.x & 31;
    size_t off = (size_t)m*1024 + (size_t)wid*256 + (size_t)lane*8;

    float4 o0 = *(const float4*)(g_o + off);
    float4 o1 = *(const float4*)(g_o + off + 4);
    float ssq = o0.x*o0.x + o0.y*o0.y + o0.z*o0.z + o0.w*o0.w
              + o1.x*o1.x + o1.y*o1.y + o1.z*o1.z + o1.w*o1.w;
#pragma unroll
    for (int s = 16; s > 0; s >>= 1) ssq += __shfl_xor_sync(0xffffffffu, ssq, s);
    float rms = rsqrtf(ssq * (1.f/256.f) + 1e-5f);

    float4 gg0 = *(const float4*)(g + off);
    float4 gg1 = *(const float4*)(g + off + 4);
    const float* wv = gnw + lane*8;

    float r[8];
    r[0] = o0.x*rms*wv[0]*(gg0.x/(1.f+expf(-gg0.x)));
    r[1] = o0.y*rms*wv[1]*(gg0.y/(1.f+expf(-gg0.y)));
    r[2] = o0.z*rms*wv[2]*(gg0.z/(1.f+expf(-gg0.z)));
    r[3] = o0.w*rms*wv[3]*(gg0.w/(1.f+expf(-gg0.w)));
    r[4] = o1.x*rms*wv[4]*(gg1.x/(1.f+expf(-gg1.x)));
    r[5] = o1.y*rms*wv[5]*(gg1.y/(1.f+expf(-gg1.y)));
    r[6] = o1.z*rms*wv[6]*(gg1.z/(1.f+expf(-gg1.z)));
    r[7] = o1.w*rms*wv[7]*(gg1.w/(1.f+expf(-gg1.w)));

#pragma unroll
    for (int i = 0; i < 8; i += 2) {
        *(__half2*)(g_oh + off + i) =
            __halves2half2(__float2half_rn(r[i]), __float2half_rn(r[i+1]));
    }
}

// ---------------------------------------------------------------------------
extern "C" void kernel_launch(void* const* d_in, const int* in_sizes, int n_in,
                              void* d_out, int out_size)
{
    (void)in_sizes; (void)n_in; (void)out_size;
    const float* x     = (const float*)d_in[0];
    const float* Wq    = (const float*)d_in[1];
    const float* Wk    = (const float*)d_in[2];
    const float* Wv    = (const float*)d_in[3];
    const float* gk_w1 = (const float*)d_in[4];
    const float* gk_w2 = (const float*)d_in[5];
    const float* gk_b2 = (const float*)d_in[6];
    const float* Wg    = (const float*)d_in[7];
    const float* gnw   = (const float*)d_in[8];
    const float* Wo    = (const float*)d_in[9];
    float* out = (float*)d_out;

    __half *xh,*xl,*wa,*wo,*oh;
    float *pq,*pk,*pd,*pv,*pg;
    cudaGetSymbolAddress((void**)&xh, g_xh);  cudaGetSymbolAddress((void**)&xl, g_xl);
    cudaGetSymbolAddress((void**)&wa, g_wa);  cudaGetSymbolAddress((void**)&wo, g_wo);
    cudaGetSymbolAddress((void**)&oh, g_oh);
    cudaGetSymbolAddress((void**)&pq, g_q);   cudaGetSymbolAddress((void**)&pk, g_k);
    cudaGetSymbolAddress((void**)&pd, g_dcy); cudaGetSymbolAddress((void**)&pv, g_v);
    cudaGetSymbolAddress((void**)&pg, g_g);

    cudaFuncSetAttribute((const void*)hgemm2<0,1>, cudaFuncAttributeMaxDynamicSharedMemorySize, SMEM3);
    cudaFuncSetAttribute((const void*)hgemm2<1,2>, cudaFuncAttributeMaxDynamicSharedMemorySize, SMEM3);

    // splits
    split_kernel<<<MM*1024/16/256, 256>>>(x, xh, xl, MM*1024);
    wsplit_kernel<<<(1024*512/8 + 255)/256, 256>>>(Wq, 512,  0,    1024*512);
    wsplit_kernel<<<(1024*512/8 + 255)/256, 256>>>(Wk, 512,  512,  1024*512);
    wsplit_kernel<<<(1024*1024/8 + 255)/256, 256>>>(Wv, 1024, 1536, 1024*1024);
    wsplit_kernel<<<(1024*1024/8 + 255)/256, 256>>>(Wg, 1024, 2560, 1024*1024);
    weff_wsplit_kernel<<<(512*1024)/256, 256>>>(gk_w1, gk_w2);
    wo_split_kernel<<<(1024*1024/8 + 255)/256, 256>>>(Wo, 1024*1024);

    dim3 blk(256);

    // GEMM1: packed q | k | decay | v | g   (N=3584, grid 28x256)
    // q,k tiles 2-term; decay/v/g tiles 1-term
    hgemm2<1,2><<<dim3(28, MM/128), blk, SMEM3>>>(
        xh, xl, wa, nullptr, 1024, NPACK, 1.f, gk_b2, pq, pk, pd, pv, pg);

    gla_rec_kernel<<<BB*4*8, 128>>>();
    epilogue_kernel<<<MM, 128>>>(pg, gnw);

    // GEMM2: out = o' @ Wo  (N=1024), 1-term
    hgemm2<0,1><<<dim3(8, MM/128), blk, SMEM3>>>(
        oh, nullptr, wo, out, 1024, 1024, 1.f, nullptr,
        nullptr, nullptr, nullptr, nullptr, nullptr);
}

// round 14
// speedup vs baseline: 1.7951x; 1.1238x over previous
#include <cuda_runtime.h>
#include <cuda_fp16.h>
#include <cstdint>

// ---------------------------------------------------------------------------
// GLA block: B=8, T=4096, D=1024, H=4, Dk=128, Dv=256
// GEMMs: pure fp16 1-term (x, weights, o' all fp16-rounded; fp32 accum).
// Calibrated error model: final rel_err ~6.5e-4 < 1e-3 gate (deterministic).
// Topology: proven R9/R11/R12 (packed GEMM1 -> rec -> epilogue -> GEMM2).
// (Resubmission of R13 — previous round was an infra failure, never measured.)
// ---------------------------------------------------------------------------

#define BB   8
#define TT   4096
#define MM   (BB*TT)          // 32768
#define QSCALE 0.08838834764831845f
#define NPACK 3584            // packed q|k|decay|v|g

// ---------------- scratch (device globals; allocation-free) ----------------
__device__ __half g_xh[MM*1024];
__device__ __half g_wa[1024*NPACK];          // packed fp16: Wq|Wk|Weff|Wv|Wg
__device__ __half g_wo[1024*1024];           // Wo fp16
__device__ float g_q[MM*512], g_k[MM*512], g_dcy[MM*512];
__device__ float g_v[MM*1024], g_g[MM*1024], g_o[MM*1024];
__device__ __half g_oh[MM*1024];

__device__ __forceinline__ void cp16(uint32_t s, const void* g) {
    asm volatile("cp.async.cg.shared.global [%0], [%1], 16;" :: "r"(s), "l"(g));
}

// ---------------------------------------------------------------------------
// fp32 -> fp16 conversion kernels
// ---------------------------------------------------------------------------
__device__ __forceinline__ void hcvt8(const float* f, uint32_t* hp)
{
#pragma unroll
    for (int j = 0; j < 4; j++) {
        __half2 hh = __halves2half2(__float2half_rn(f[2*j]), __float2half_rn(f[2*j+1]));
        hp[j] = *(uint32_t*)&hh;
    }
}

__global__ void cvt_kernel(const float* __restrict__ s,
                           __half* __restrict__ h, int n)
{
    int i = (blockIdx.x * blockDim.x + threadIdx.x) * 16;
    if (i >= n) return;
    float4 v0 = *(const float4*)(s + i);
    float4 v1 = *(const float4*)(s + i + 4);
    float4 v2 = *(const float4*)(s + i + 8);
    float4 v3 = *(const float4*)(s + i + 12);
    float f[16] = {v0.x, v0.y, v0.z, v0.w, v1.x, v1.y, v1.z, v1.w,
                   v2.x, v2.y, v2.z, v2.w, v3.x, v3.y, v3.z, v3.w};
    uint32_t hp[4];
    hcvt8(f, hp);
    *(uint4*)(h + i) = make_uint4(hp[0], hp[1], hp[2], hp[3]);
    hcvt8(f + 8, hp);
    *(uint4*)(h + i + 8) = make_uint4(hp[0], hp[1], hp[2], hp[3]);
}

// W[K,Nsrc] fp32 -> packed g_wa fp16 at column offset
__global__ void wcvt_kernel(const float* __restrict__ src, int Nsrc,
                            int coloff, int total)
{
    int i = (blockIdx.x * blockDim.x + threadIdx.x) * 8;
    if (i >= total) return;
    int k = i / Nsrc, n = i % Nsrc;
    float4 v0 = *(const float4*)(src + i);
    float4 v1 = *(const float4*)(src + i + 4);
    float f[8] = {v0.x, v0.y, v0.z, v0.w, v1.x, v1.y, v1.z, v1.w};
    uint32_t hp[4];
    hcvt8(f, hp);
    *(uint4*)(g_wa + (size_t)k * NPACK + coloff + n) = make_uint4(hp[0], hp[1], hp[2], hp[3]);
}

__global__ void wo_cvt_kernel(const float* __restrict__ src, int total)
{
    int i = (blockIdx.x * blockDim.x + threadIdx.x) * 8;
    if (i >= total) return;
    float4 v0 = *(const float4*)(src + i);
    float4 v1 = *(const float4*)(src + i + 4);
    float f[8] = {v0.x, v0.y, v0.z, v0.w, v1.x, v1.y, v1.z, v1.w};
    uint32_t hp[4];
    hcvt8(f, hp);
    *(uint4*)(g_wo + i) = make_uint4(hp[0], hp[1], hp[2], hp[3]);
}

// Weff = gk_w1 @ gk_w2 (1024x16 @ 16x512) -> packed cols [1024,1536), fp16
__global__ void weff_cvt_kernel(const float* __restrict__ w1,
                                const float* __restrict__ w2)
{
    int idx = blockIdx.x * blockDim.x + threadIdx.x;   // k*512 + n
    int kk = idx >> 9, n = idx & 511;
    float s = 0.f;
#pragma unroll
    for (int r = 0; r < 16; r++)
        s += w1[kk * 16 + r] * w2[r * 512 + n];
    g_wa[(size_t)kk * NPACK + 1024 + n] = __float2half_rn(s);
}

// ---------------------------------------------------------------------------
// fp16 1-term GEMM: C[M,N] = A@B, fp32 accum.
// BM=BN=128, BK=32, 3-stage cp.async (wait_group 1), warp tile 64x32.
// FUSED=1: packed epilogue routing (q|k|decay|v|g).
// ---------------------------------------------------------------------------
#define A_T 5120   // 128*40 elems per stage
#define B_T 4352   // 32*136 elems per stage
#define STG_B ((A_T + B_T) * 2)        // 18944 B per stage
#define SMEM3 (3 * STG_B)              // 56832 B

#define LDSM_X4(R0,R1,R2,R3,ADDR) \
    asm volatile("ldmatrix.sync.aligned.m8n8.x4.shared.b16 {%0,%1,%2,%3}, [%4];" \
        : "=r"(R0),"=r"(R1),"=r"(R2),"=r"(R3) : "r"(ADDR))
#define LDSM_X4T(R0,R1,R2,R3,ADDR) \
    asm volatile("ldmatrix.sync.aligned.m8n8.x4.trans.shared.b16 {%0,%1,%2,%3}, [%4];" \
        : "=r"(R0),"=r"(R1),"=r"(R2),"=r"(R3) : "r"(ADDR))
#define MMAH(D,A,B) \
    asm volatile("mma.sync.aligned.m16n8k16.row.col.f32.f16.f16.f32 " \
        "{%0,%1,%2,%3}, {%4,%5,%6,%7}, {%8,%9}, {%0,%1,%2,%3};" \
        : "+f"(D[0]),"+f"(D[1]),"+f"(D[2]),"+f"(D[3]) \
        : "r"(A[0]),"r"(A[1]),"r"(A[2]),"r"(A[3]),"r"(B[0]),"r"(B[1]))

template<int FUSED>
__global__ __launch_bounds__(256)
void hgemm1(const __half* __restrict__ Ah, const __half* __restrict__ Bw,
            float* __restrict__ C, int K, int ldB, float scale,
            const float* __restrict__ bias,
            float* __restrict__ pq, float* __restrict__ pk, float* __restrict__ pd,
            float* __restrict__ pv, float* __restrict__ pgg)
{
    extern __shared__ __align__(16) __half sm[];

    const int tid = threadIdx.x;
    const int bn = blockIdx.x, bm = blockIdx.y;
    const int lane = tid & 31, wid = tid >> 5;
    const int wm = (wid & 1) * 64;
    const int wn = (wid >> 1) * 32;

    const int ar = tid >> 2, ac = (tid & 3) * 8;
    const int br = tid >> 4, bc = (tid & 15) * 8;

    const __half* gAh = Ah + (size_t)(bm*128 + ar) * K + ac;
    const __half* gB  = Bw + (size_t)br * ldB + bn*128 + bc;

    const uint32_t u0 = (uint32_t)__cvta_generic_to_shared(sm);
    const uint32_t a_st0 = (ar*40 + ac)*2, a_st1 = ((ar+64)*40 + ac)*2;
    const uint32_t b_st0 = (br*136 + bc)*2, b_st1 = ((br+16)*136 + bc)*2;

    float acc[4][4][4];
#pragma unroll
    for (int i = 0; i < 4; i++)
#pragma unroll
        for (int j = 0; j < 4; j++)
#pragma unroll
            for (int r = 0; r < 4; r++) acc[i][j][r] = 0.f;

    const int KT = K >> 5;

    auto load_stage = [&](int kt, int st) {
        const __half* pAh = gAh + kt*32;
        const __half* pB  = gB  + (size_t)kt*32*ldB;
        uint32_t sb = u0 + (uint32_t)st * STG_B;
        cp16(sb + a_st0, pAh);
        cp16(sb + a_st1, pAh + (size_t)64*K);
        cp16(sb + 2*A_T + b_st0, pB);
        cp16(sb + 2*A_T + b_st1, pB + (size_t)16*ldB);
        asm volatile("cp.async.commit_group;");
    };

    const int arow = wm + (lane & 15);
    const int acol = (lane >> 4) * 8;
    const int bkr  = (lane & 15);
    const int bcol = wn + ((lane >> 4) * 8);

    load_stage(0, 0);
    load_stage(1, 1);
    for (int kt = 0; kt < KT; kt++) {
        if (kt + 1 < KT)
            asm volatile("cp.async.wait_group 1;" ::: "memory");
        else
            asm volatile("cp.async.wait_group 0;" ::: "memory");
        __syncthreads();
        if (kt + 2 < KT) load_stage(kt + 2, (kt + 2) % 3);

        uint32_t sb  = u0 + (uint32_t)(kt % 3) * STG_B;
        uint32_t aBH = sb;
        uint32_t bBH = sb + 2*A_T;
#pragma unroll
        for (int ks = 0; ks < 2; ks++) {
            uint32_t ah[4][4], bh[4][2];
#pragma unroll
            for (int mi = 0; mi < 4; mi++) {
                uint32_t off = ((arow + mi*16)*40 + ks*16 + acol) * 2;
                LDSM_X4(ah[mi][0], ah[mi][1], ah[mi][2], ah[mi][3], aBH + off);
            }
#pragma unroll
            for (int p = 0; p < 2; p++) {
                uint32_t off = ((ks*16 + bkr)*136 + bcol + p*16) * 2;
                LDSM_X4T(bh[2*p][0], bh[2*p][1], bh[2*p+1][0], bh[2*p+1][1], bBH + off);
            }
#pragma unroll
            for (int mi = 0; mi < 4; mi++)
#pragma unroll
                for (int ni = 0; ni < 4; ni++) MMAH(acc[mi][ni], ah[mi], bh[ni]);
        }
    }

    float* dst; int ldo, coff, kind; float sc = scale;
    if (FUSED) {
        if      (bn < 4)  { dst = pq;  ldo = 512;  coff = 0;    kind = 0; sc = QSCALE; }
        else if (bn < 8)  { dst = pk;  ldo = 512;  coff = 512;  kind = 1; }
        else if (bn < 12) { dst = pd;  ldo = 512;  coff = 1024; kind = 2; }
        else if (bn < 20) { dst = pv;  ldo = 1024; coff = 1536; kind = 1; }
        else              { dst = pgg; ldo = 1024; coff = 2560; kind = 1; }
    } else {
        dst = C; ldo = ldB; coff = 0; kind = 0;
    }

#pragma unroll
    for (int mi = 0; mi < 4; mi++) {
        int r0 = bm*128 + wm + mi*16 + (lane >> 2);
#pragma unroll
        for (int ni = 0; ni < 4; ni++) {
            int gc = bn*128 + wn + ni*8 + (lane & 3)*2;
            int c = gc - coff;
            float o0 = acc[mi][ni][0], o1 = acc[mi][ni][1];
            float o2 = acc[mi][ni][2], o3 = acc[mi][ni][3];
            if (kind == 0) {
                o0 *= sc; o1 *= sc; o2 *= sc; o3 *= sc;
            } else if (kind == 2) {
                float b0 = bias[c], b1 = bias[c + 1];
                float z, sp;
                z = o0 + b0; sp = fmaxf(-z,0.f) + log1pf(expf(-fabsf(z))); o0 = expf(-sp*0.0625f);
                z = o1 + b1; sp = fmaxf(-z,0.f) + log1pf(expf(-fabsf(z))); o1 = expf(-sp*0.0625f);
                z = o2 + b0; sp = fmaxf(-z,0.f) + log1pf(expf(-fabsf(z))); o2 = expf(-sp*0.0625f);
                z = o3 + b1; sp = fmaxf(-z,0.f) + log1pf(expf(-fabsf(z))); o3 = expf(-sp*0.0625f);
            }
            *(float2*)(dst + (size_t)r0 * ldo + c)       = make_float2(o0, o1);
            *(float2*)(dst + (size_t)(r0 + 8) * ldo + c) = make_float2(o2, o3);
        }
    }
}

// ---------------------------------------------------------------------------
// GLA recurrence (R9/R11/R12 proven version, unchanged)
// ---------------------------------------------------------------------------
#define RC 8
#define NCH (TT/RC)

__global__ __launch_bounds__(128)
void gla_rec_kernel()
{
    __shared__ __align__(16) float sq[2][RC*128], sk[2][RC*128], sd[2][RC*128];
    __shared__ __align__(16) float sv[2][RC*32];
    __shared__ float red[2][4][RC*32];

    int bid = blockIdx.x;
    int dvt = bid & 7, h = (bid >> 3) & 3, b = bid >> 5;
    int tid = threadIdx.x, c = tid & 31, w = tid >> 5;

    size_t base_qk = ((size_t)b*TT)*512 + (size_t)h*128;
    size_t base_v  = ((size_t)b*TT)*1024 + (size_t)h*256 + (size_t)dvt*32;
    const float* qp = g_q + base_qk;
    const float* kp = g_k + base_qk;
    const float* dp = g_dcy + base_qk;
    const float* vp = g_v + base_v;
    float* op = g_o + base_v;

    const uint32_t uq = (uint32_t)__cvta_generic_to_shared(&sq[0][0]);
    const uint32_t uk = (uint32_t)__cvta_generic_to_shared(&sk[0][0]);
    const uint32_t ud = (uint32_t)__cvta_generic_to_shared(&sd[0][0]);
    const uint32_t uv = (uint32_t)__cvta_generic_to_shared(&sv[0][0]);

    auto load = [&](int t0, int bf) {
        uint32_t bo = (uint32_t)bf * (RC*128*4);
#pragma unroll
        for (int j = 0; j < 2; j++) {
            int idx = tid + j*128;
            int s = idx >> 5, seg = idx & 31;
            uint32_t so = (uint32_t)((s*128 + seg*4) * 4);
            size_t go = (size_t)(t0 + s)*512 + seg*4;
            cp16(uq + bo + so, qp + go);
            cp16(uk + bo + so, kp + go);
            cp16(ud + bo + so, dp + go);
        }
        if (tid < 64) {
            int s = tid >> 3, seg = tid & 7;
            cp16(uv + (uint32_t)bf*(RC*32*4) + (uint32_t)((s*32 + seg*4)*4),
                 vp + (size_t)(t0 + s)*1024 + seg*4);
        }
        asm volatile("cp.async.commit_group;" ::: "memory");
    };

    unsigned long long S2[16];
#pragma unroll
    for (int i = 0; i < 16; i++) S2[i] = 0ull;

    load(0, 0);
    for (int ci = 0; ci < NCH; ci++) {
        asm volatile("cp.async.wait_group 0;" ::: "memory");
        __syncthreads();
        if (ci + 1 < NCH) load((ci + 1)*RC, (ci + 1) & 1);

        int bf = ci & 1, t0 = ci*RC;
#pragma unroll 2
        for (int s = 0; s < RC; s++) {
            const ulonglong2* q4 = (const ulonglong2*)(&sq[bf][s*128 + w*32]);
            const ulonglong2* k4 = (const ulonglong2*)(&sk[bf][s*128 + w*32]);
            const ulonglong2* d4 = (const ulonglong2*)(&sd[bf][s*128 + w*32]);
            float vj = sv[bf][s*32 + c];
            unsigned long long vv;
            asm("mov.b64 %0, {%1, %1};" : "=l"(vv) : "f"(vj));
            unsigned long long ac[4] = {0ull, 0ull, 0ull, 0ull};
#pragma unroll
            for (int i = 0; i < 8; i++) {
                ulonglong2 qv = q4[i], kv = k4[i], dv = d4[i];
                unsigned long long t;
                asm("mul.rn.f32x2 %0, %1, %2;" : "=l"(t) : "l"(kv.x), "l"(vv));
                asm("fma.rn.f32x2 %0, %1, %2, %3;" : "=l"(S2[2*i])   : "l"(dv.x), "l"(S2[2*i]),   "l"(t));
                asm("fma.rn.f32x2 %0, %1, %2, %3;" : "=l"(ac[(2*i)&3])   : "l"(qv.x), "l"(S2[2*i]),   "l"(ac[(2*i)&3]));
                asm("mul.rn.f32x2 %0, %1, %2;" : "=l"(t) : "l"(kv.y), "l"(vv));
                asm("fma.rn.f32x2 %0, %1, %2, %3;" : "=l"(S2[2*i+1]) : "l"(dv.y), "l"(S2[2*i+1]), "l"(t));
                asm("fma.rn.f32x2 %0, %1, %2, %3;" : "=l"(ac[(2*i+1)&3]) : "l"(qv.y), "l"(S2[2*i+1]), "l"(ac[(2*i+1)&3]));
            }
            float p = 0.f;
#pragma unroll
            for (int j = 0; j < 4; j++) {
                float x0, x1;
                asm("mov.b64 {%0, %1}, %2;" : "=f"(x0), "=f"(x1) : "l"(ac[j]));
                p += x0 + x1;
            }
            red[bf][w][s*32 + c] = p;
        }
        __syncthreads();
#pragma unroll
        for (int j = 0; j < 2; j++) {
            int idx = tid + j*128;
            int s = idx >> 5, cc = idx & 31;
            float v = red[bf][0][s*32 + cc] + red[bf][1][s*32 + cc]
                    + red[bf][2][s*32 + cc] + red[bf][3][s*32 + cc];
            op[(size_t)(t0 + s)*1024 + cc] = v;
        }
    }
}

// ---------------------------------------------------------------------------
// RMSNorm * g_norm_w * swish(g) -> fp16 for final GEMM
// ---------------------------------------------------------------------------
__global__ __launch_bounds__(128)
void epilogue_kernel(const float* __restrict__ g, const float* __restrict__ gnw)
{
    int m = blockIdx.x, wid = threadIdx.x >> 5, lane = threadIdx.x & 31;
    size_t off = (size_t)m*1024 + (size_t)wid*256 + (size_t)lane*8;

    float4 o0 = *(const float4*)(g_o + off);
    float4 o1 = *(const float4*)(g_o + off + 4);
    float ssq = o0.x*o0.x + o0.y*o0.y + o0.z*o0.z + o0.w*o0.w
              + o1.x*o1.x + o1.y*o1.y + o1.z*o1.z + o1.w*o1.w;
#pragma unroll
    for (int s = 16; s > 0; s >>= 1) ssq += __shfl_xor_sync(0xffffffffu, ssq, s);
    float rms = rsqrtf(ssq * (1.f/256.f) + 1e-5f);

    float4 gg0 = *(const float4*)(g + off);
    float4 gg1 = *(const float4*)(g + off + 4);
    const float* wv = gnw + lane*8;

    float r[8];
    r[0] = o0.x*rms*wv[0]*(gg0.x/(1.f+expf(-gg0.x)));
    r[1] = o0.y*rms*wv[1]*(gg0.y/(1.f+expf(-gg0.y)));
    r[2] = o0.z*rms*wv[2]*(gg0.z/(1.f+expf(-gg0.z)));
    r[3] = o0.w*rms*wv[3]*(gg0.w/(1.f+expf(-gg0.w)));
    r[4] = o1.x*rms*wv[4]*(gg1.x/(1.f+expf(-gg1.x)));
    r[5] = o1.y*rms*wv[5]*(gg1.y/(1.f+expf(-gg1.y)));
    r[6] = o1.z*rms*wv[6]*(gg1.z/(1.f+expf(-gg1.z)));
    r[7] = o1.w*rms*wv[7]*(gg1.w/(1.f+expf(-gg1.w)));

#pragma unroll
    for (int i = 0; i < 8; i += 2) {
        *(__half2*)(g_oh + off + i) =
            __halves2half2(__float2half_rn(r[i]), __float2half_rn(r[i+1]));
    }
}

// ---------------------------------------------------------------------------
extern "C" void kernel_launch(void* const* d_in, const int* in_sizes, int n_in,
                              void* d_out, int out_size)
{
    (void)in_sizes; (void)n_in; (void)out_size;
    const float* x     = (const float*)d_in[0];
    const float* Wq    = (const float*)d_in[1];
    const float* Wk    = (const float*)d_in[2];
    const float* Wv    = (const float*)d_in[3];
    const float* gk_w1 = (const float*)d_in[4];
    const float* gk_w2 = (const float*)d_in[5];
    const float* gk_b2 = (const float*)d_in[6];
    const float* Wg    = (const float*)d_in[7];
    const float* gnw   = (const float*)d_in[8];
    const float* Wo    = (const float*)d_in[9];
    float* out = (float*)d_out;

    __half *xh,*wa,*wo,*oh;
    float *pq,*pk,*pd,*pv,*pg;
    cudaGetSymbolAddress((void**)&xh, g_xh);
    cudaGetSymbolAddress((void**)&wa, g_wa);  cudaGetSymbolAddress((void**)&wo, g_wo);
    cudaGetSymbolAddress((void**)&oh, g_oh);
    cudaGetSymbolAddress((void**)&pq, g_q);   cudaGetSymbolAddress((void**)&pk, g_k);
    cudaGetSymbolAddress((void**)&pd, g_dcy); cudaGetSymbolAddress((void**)&pv, g_v);
    cudaGetSymbolAddress((void**)&pg, g_g);

    cudaFuncSetAttribute((const void*)hgemm1<0>, cudaFuncAttributeMaxDynamicSharedMemorySize, SMEM3);
    cudaFuncSetAttribute((const void*)hgemm1<1>, cudaFuncAttributeMaxDynamicSharedMemorySize, SMEM3);

    // conversions
    cvt_kernel<<<MM*1024/16/256, 256>>>(x, xh, MM*1024);
    wcvt_kernel<<<(1024*512/8 + 255)/256, 256>>>(Wq, 512,  0,    1024*512);
    wcvt_kernel<<<(1024*512/8 + 255)/256, 256>>>(Wk, 512,  512,  1024*512);
    wcvt_kernel<<<(1024*1024/8 + 255)/256, 256>>>(Wv, 1024, 1536, 1024*1024);
    wcvt_kernel<<<(1024*1024/8 + 255)/256, 256>>>(Wg, 1024, 2560, 1024*1024);
    weff_cvt_kernel<<<(512*1024)/256, 256>>>(gk_w1, gk_w2);
    wo_cvt_kernel<<<(1024*1024/8 + 255)/256, 256>>>(Wo, 1024*1024);

    dim3 blk(256);

    // GEMM1: packed q | k | decay | v | g   (N=3584, grid 28x256)
    hgemm1<1><<<dim3(28, MM/128), blk, SMEM3>>>(
        xh, wa, nullptr, 1024, NPACK, 1.f, gk_b2, pq, pk, pd, pv, pg);

    gla_rec_kernel<<<BB*4*8, 128>>>();
    epilogue_kernel<<<MM, 128>>>(pg, gnw);

    // GEMM2: out = o' @ Wo  (N=1024)
    hgemm1<0><<<dim3(8, MM/128), blk, SMEM3>>>(
        oh, wo, out, 1024, 1024, 1.f, nullptr,
        nullptr, nullptr, nullptr, nullptr, nullptr);
}

// round 17
// speedup vs baseline: 1.8094x; 1.0080x over previous
#include <cuda_runtime.h>
#include <cuda_fp16.h>
#include <cstdint>

// ---------------------------------------------------------------------------
// GLA block: B=8, T=4096, D=1024, H=4, Dk=128, Dv=256
// GEMMs: pure fp16 1-term (fp32 accum), rel_err 6.7e-4 (verified R14).
// This round: GEMM at 2 CTAs/SM (launch_bounds(256,2); 1-term fits 128 regs,
// 2x56.8KB smem fits 228KB) to fill residual issue bubbles.
// ---------------------------------------------------------------------------

#define BB   8
#define TT   4096
#define MM   (BB*TT)          // 32768
#define QSCALE 0.08838834764831845f
#define NPACK 3584            // packed q|k|decay|v|g

// ---------------- scratch (device globals; allocation-free) ----------------
__device__ __half g_xh[MM*1024];
__device__ __half g_wa[1024*NPACK];          // packed fp16: Wq|Wk|Weff|Wv|Wg
__device__ __half g_wo[1024*1024];           // Wo fp16
__device__ float g_q[MM*512], g_k[MM*512], g_dcy[MM*512];
__device__ float g_v[MM*1024], g_g[MM*1024], g_o[MM*1024];
__device__ __half g_oh[MM*1024];

__device__ __forceinline__ void cp16(uint32_t s, const void* g) {
    asm volatile("cp.async.cg.shared.global [%0], [%1], 16;" :: "r"(s), "l"(g));
}

// ---------------------------------------------------------------------------
// fp32 -> fp16 conversion kernels
// ---------------------------------------------------------------------------
__device__ __forceinline__ void hcvt8(const float* f, uint32_t* hp)
{
#pragma unroll
    for (int j = 0; j < 4; j++) {
        __half2 hh = __halves2half2(__float2half_rn(f[2*j]), __float2half_rn(f[2*j+1]));
        hp[j] = *(uint32_t*)&hh;
    }
}

__global__ void cvt_kernel(const float* __restrict__ s,
                           __half* __restrict__ h, int n)
{
    int i = (blockIdx.x * blockDim.x + threadIdx.x) * 16;
    if (i >= n) return;
    float4 v0 = *(const float4*)(s + i);
    float4 v1 = *(const float4*)(s + i + 4);
    float4 v2 = *(const float4*)(s + i + 8);
    float4 v3 = *(const float4*)(s + i + 12);
    float f[16] = {v0.x, v0.y, v0.z, v0.w, v1.x, v1.y, v1.z, v1.w,
                   v2.x, v2.y, v2.z, v2.w, v3.x, v3.y, v3.z, v3.w};
    uint32_t hp[4];
    hcvt8(f, hp);
    *(uint4*)(h + i) = make_uint4(hp[0], hp[1], hp[2], hp[3]);
    hcvt8(f + 8, hp);
    *(uint4*)(h + i + 8) = make_uint4(hp[0], hp[1], hp[2], hp[3]);
}

// W[K,Nsrc] fp32 -> packed g_wa fp16 at column offset
__global__ void wcvt_kernel(const float* __restrict__ src, int Nsrc,
                            int coloff, int total)
{
    int i = (blockIdx.x * blockDim.x + threadIdx.x) * 8;
    if (i >= total) return;
    int k = i / Nsrc, n = i % Nsrc;
    float4 v0 = *(const float4*)(src + i);
    float4 v1 = *(const float4*)(src + i + 4);
    float f[8] = {v0.x, v0.y, v0.z, v0.w, v1.x, v1.y, v1.z, v1.w};
    uint32_t hp[4];
    hcvt8(f, hp);
    *(uint4*)(g_wa + (size_t)k * NPACK + coloff + n) = make_uint4(hp[0], hp[1], hp[2], hp[3]);
}

__global__ void wo_cvt_kernel(const float* __restrict__ src, int total)
{
    int i = (blockIdx.x * blockDim.x + threadIdx.x) * 8;
    if (i >= total) return;
    float4 v0 = *(const float4*)(src + i);
    float4 v1 = *(const float4*)(src + i + 4);
    float f[8] = {v0.x, v0.y, v0.z, v0.w, v1.x, v1.y, v1.z, v1.w};
    uint32_t hp[4];
    hcvt8(f, hp);
    *(uint4*)(g_wo + i) = make_uint4(hp[0], hp[1], hp[2], hp[3]);
}

// Weff = gk_w1 @ gk_w2 (1024x16 @ 16x512) -> packed cols [1024,1536), fp16
__global__ void weff_cvt_kernel(const float* __restrict__ w1,
                                const float* __restrict__ w2)
{
    int idx = blockIdx.x * blockDim.x + threadIdx.x;   // k*512 + n
    int kk = idx >> 9, n = idx & 511;
    float s = 0.f;
#pragma unroll
    for (int r = 0; r < 16; r++)
        s += w1[kk * 16 + r] * w2[r * 512 + n];
    g_wa[(size_t)kk * NPACK + 1024 + n] = __float2half_rn(s);
}

// ---------------------------------------------------------------------------
// fp16 1-term GEMM: C[M,N] = A@B, fp32 accum.
// BM=BN=128, BK=32, 3-stage cp.async (wait_group 1), warp tile 64x32.
// 2 CTAs/SM (128-reg cap; ~120 regs needed -> no spill expected).
// FUSED=1: packed epilogue routing (q|k|decay|v|g).
// ---------------------------------------------------------------------------
#define A_T 5120   // 128*40 elems per stage
#define B_T 4352   // 32*136 elems per stage
#define STG_B ((A_T + B_T) * 2)        // 18944 B per stage
#define SMEM3 (3 * STG_B)              // 56832 B

#define LDSM_X4(R0,R1,R2,R3,ADDR) \
    asm volatile("ldmatrix.sync.aligned.m8n8.x4.shared.b16 {%0,%1,%2,%3}, [%4];" \
        : "=r"(R0),"=r"(R1),"=r"(R2),"=r"(R3) : "r"(ADDR))
#define LDSM_X4T(R0,R1,R2,R3,ADDR) \
    asm volatile("ldmatrix.sync.aligned.m8n8.x4.trans.shared.b16 {%0,%1,%2,%3}, [%4];" \
        : "=r"(R0),"=r"(R1),"=r"(R2),"=r"(R3) : "r"(ADDR))
#define MMAH(D,A,B) \
    asm volatile("mma.sync.aligned.m16n8k16.row.col.f32.f16.f16.f32 " \
        "{%0,%1,%2,%3}, {%4,%5,%6,%7}, {%8,%9}, {%0,%1,%2,%3};" \
        : "+f"(D[0]),"+f"(D[1]),"+f"(D[2]),"+f"(D[3]) \
        : "r"(A[0]),"r"(A[1]),"r"(A[2]),"r"(A[3]),"r"(B[0]),"r"(B[1]))

template<int FUSED>
__global__ __launch_bounds__(256, 2)
void hgemm1(const __half* __restrict__ Ah, const __half* __restrict__ Bw,
            float* __restrict__ C, int K, int ldB, float scale,
            const float* __restrict__ bias,
            float* __restrict__ pq, float* __restrict__ pk, float* __restrict__ pd,
            float* __restrict__ pv, float* __restrict__ pgg)
{
    extern __shared__ __align__(16) __half sm[];

    const int tid = threadIdx.x;
    const int bn = blockIdx.x, bm = blockIdx.y;
    const int lane = tid & 31, wid = tid >> 5;
    const int wm = (wid & 1) * 64;
    const int wn = (wid >> 1) * 32;

    const int ar = tid >> 2, ac = (tid & 3) * 8;
    const int br = tid >> 4, bc = (tid & 15) * 8;

    const __half* gAh = Ah + (size_t)(bm*128 + ar) * K + ac;
    const __half* gB  = Bw + (size_t)br * ldB + bn*128 + bc;

    const uint32_t u0 = (uint32_t)__cvta_generic_to_shared(sm);
    const uint32_t a_st0 = (ar*40 + ac)*2, a_st1 = ((ar+64)*40 + ac)*2;
    const uint32_t b_st0 = (br*136 + bc)*2, b_st1 = ((br+16)*136 + bc)*2;

    float acc[4][4][4];
#pragma unroll
    for (int i = 0; i < 4; i++)
#pragma unroll
        for (int j = 0; j < 4; j++)
#pragma unroll
            for (int r = 0; r < 4; r++) acc[i][j][r] = 0.f;

    const int KT = K >> 5;

    auto load_stage = [&](int kt, int st) {
        const __half* pAh = gAh + kt*32;
        const __half* pB  = gB  + (size_t)kt*32*ldB;
        uint32_t sb = u0 + (uint32_t)st * STG_B;
        cp16(sb + a_st0, pAh);
        cp16(sb + a_st1, pAh + (size_t)64*K);
        cp16(sb + 2*A_T + b_st0, pB);
        cp16(sb + 2*A_T + b_st1, pB + (size_t)16*ldB);
        asm volatile("cp.async.commit_group;");
    };

    const int arow = wm + (lane & 15);
    const int acol = (lane >> 4) * 8;
    const int bkr  = (lane & 15);
    const int bcol = wn + ((lane >> 4) * 8);

    load_stage(0, 0);
    load_stage(1, 1);
    for (int kt = 0; kt < KT; kt++) {
        if (kt + 1 < KT)
            asm volatile("cp.async.wait_group 1;" ::: "memory");
        else
            asm volatile("cp.async.wait_group 0;" ::: "memory");
        __syncthreads();
        if (kt + 2 < KT) load_stage(kt + 2, (kt + 2) % 3);

        uint32_t sb  = u0 + (uint32_t)(kt % 3) * STG_B;
        uint32_t aBH = sb;
        uint32_t bBH = sb + 2*A_T;
#pragma unroll
        for (int ks = 0; ks < 2; ks++) {
            uint32_t ah[4][4], bh[4][2];
#pragma unroll
            for (int mi = 0; mi < 4; mi++) {
                uint32_t off = ((arow + mi*16)*40 + ks*16 + acol) * 2;
                LDSM_X4(ah[mi][0], ah[mi][1], ah[mi][2], ah[mi][3], aBH + off);
            }
#pragma unroll
            for (int p = 0; p < 2; p++) {
                uint32_t off = ((ks*16 + bkr)*136 + bcol + p*16) * 2;
                LDSM_X4T(bh[2*p][0], bh[2*p][1], bh[2*p+1][0], bh[2*p+1][1], bBH + off);
            }
#pragma unroll
            for (int mi = 0; mi < 4; mi++)
#pragma unroll
                for (int ni = 0; ni < 4; ni++) MMAH(acc[mi][ni], ah[mi], bh[ni]);
        }
    }

    float* dst; int ldo, coff, kind; float sc = scale;
    if (FUSED) {
        if      (bn < 4)  { dst = pq;  ldo = 512;  coff = 0;    kind = 0; sc = QSCALE; }
        else if (bn < 8)  { dst = pk;  ldo = 512;  coff = 512;  kind = 1; }
        else if (bn < 12) { dst = pd;  ldo = 512;  coff = 1024; kind = 2; }
        else if (bn < 20) { dst = pv;  ldo = 1024; coff = 1536; kind = 1; }
        else              { dst = pgg; ldo = 1024; coff = 2560; kind = 1; }
    } else {
        dst = C; ldo = ldB; coff = 0; kind = 0;
    }

#pragma unroll
    for (int mi = 0; mi < 4; mi++) {
        int r0 = bm*128 + wm + mi*16 + (lane >> 2);
#pragma unroll
        for (int ni = 0; ni < 4; ni++) {
            int gc = bn*128 + wn + ni*8 + (lane & 3)*2;
            int c = gc - coff;
            float o0 = acc[mi][ni][0], o1 = acc[mi][ni][1];
            float o2 = acc[mi][ni][2], o3 = acc[mi][ni][3];
            if (kind == 0) {
                o0 *= sc; o1 *= sc; o2 *= sc; o3 *= sc;
            } else if (kind == 2) {
                float b0 = bias[c], b1 = bias[c + 1];
                float z, sp;
                z = o0 + b0; sp = fmaxf(-z,0.f) + log1pf(expf(-fabsf(z))); o0 = expf(-sp*0.0625f);
                z = o1 + b1; sp = fmaxf(-z,0.f) + log1pf(expf(-fabsf(z))); o1 = expf(-sp*0.0625f);
                z = o2 + b0; sp = fmaxf(-z,0.f) + log1pf(expf(-fabsf(z))); o2 = expf(-sp*0.0625f);
                z = o3 + b1; sp = fmaxf(-z,0.f) + log1pf(expf(-fabsf(z))); o3 = expf(-sp*0.0625f);
            }
            *(float2*)(dst + (size_t)r0 * ldo + c)       = make_float2(o0, o1);
            *(float2*)(dst + (size_t)(r0 + 8) * ldo + c) = make_float2(o2, o3);
        }
    }
}

// ---------------------------------------------------------------------------
// GLA recurrence (R9/R11/R12/R14 proven version, unchanged)
// ---------------------------------------------------------------------------
#define RC 8
#define NCH (TT/RC)

__global__ __launch_bounds__(128)
void gla_rec_kernel()
{
    __shared__ __align__(16) float sq[2][RC*128], sk[2][RC*128], sd[2][RC*128];
    __shared__ __align__(16) float sv[2][RC*32];
    __shared__ float red[2][4][RC*32];

    int bid = blockIdx.x;
    int dvt = bid & 7, h = (bid >> 3) & 3, b = bid >> 5;
    int tid = threadIdx.x, c = tid & 31, w = tid >> 5;

    size_t base_qk = ((size_t)b*TT)*512 + (size_t)h*128;
    size_t base_v  = ((size_t)b*TT)*1024 + (size_t)h*256 + (size_t)dvt*32;
    const float* qp = g_q + base_qk;
    const float* kp = g_k + base_qk;
    const float* dp = g_dcy + base_qk;
    const float* vp = g_v + base_v;
    float* op = g_o + base_v;

    const uint32_t uq = (uint32_t)__cvta_generic_to_shared(&sq[0][0]);
    const uint32_t uk = (uint32_t)__cvta_generic_to_shared(&sk[0][0]);
    const uint32_t ud = (uint32_t)__cvta_generic_to_shared(&sd[0][0]);
    const uint32_t uv = (uint32_t)__cvta_generic_to_shared(&sv[0][0]);

    auto load = [&](int t0, int bf) {
        uint32_t bo = (uint32_t)bf * (RC*128*4);
#pragma unroll
        for (int j = 0; j < 2; j++) {
            int idx = tid + j*128;
            int s = idx >> 5, seg = idx & 31;
            uint32_t so = (uint32_t)((s*128 + seg*4) * 4);
            size_t go = (size_t)(t0 + s)*512 + seg*4;
            cp16(uq + bo + so, qp + go);
            cp16(uk + bo + so, kp + go);
            cp16(ud + bo + so, dp + go);
        }
        if (tid < 64) {
            int s = tid >> 3, seg = tid & 7;
            cp16(uv + (uint32_t)bf*(RC*32*4) + (uint32_t)((s*32 + seg*4)*4),
                 vp + (size_t)(t0 + s)*1024 + seg*4);
        }
        asm volatile("cp.async.commit_group;" ::: "memory");
    };

    unsigned long long S2[16];
#pragma unroll
    for (int i = 0; i < 16; i++) S2[i] = 0ull;

    load(0, 0);
    for (int ci = 0; ci < NCH; ci++) {
        asm volatile("cp.async.wait_group 0;" ::: "memory");
        __syncthreads();
        if (ci + 1 < NCH) load((ci + 1)*RC, (ci + 1) & 1);

        int bf = ci & 1, t0 = ci*RC;
#pragma unroll 2
        for (int s = 0; s < RC; s++) {
            const ulonglong2* q4 = (const ulonglong2*)(&sq[bf][s*128 + w*32]);
            const ulonglong2* k4 = (const ulonglong2*)(&sk[bf][s*128 + w*32]);
            const ulonglong2* d4 = (const ulonglong2*)(&sd[bf][s*128 + w*32]);
            float vj = sv[bf][s*32 + c];
            unsigned long long vv;
            asm("mov.b64 %0, {%1, %1};" : "=l"(vv) : "f"(vj));
            unsigned long long ac[4] = {0ull, 0ull, 0ull, 0ull};
#pragma unroll
            for (int i = 0; i < 8; i++) {
                ulonglong2 qv = q4[i], kv = k4[i], dv = d4[i];
                unsigned long long t;
                asm("mul.rn.f32x2 %0, %1, %2;" : "=l"(t) : "l"(kv.x), "l"(vv));
                asm("fma.rn.f32x2 %0, %1, %2, %3;" : "=l"(S2[2*i])   : "l"(dv.x), "l"(S2[2*i]),   "l"(t));
                asm("fma.rn.f32x2 %0, %1, %2, %3;" : "=l"(ac[(2*i)&3])   : "l"(qv.x), "l"(S2[2*i]),   "l"(ac[(2*i)&3]));
                asm("mul.rn.f32x2 %0, %1, %2;" : "=l"(t) : "l"(kv.y), "l"(vv));
                asm("fma.rn.f32x2 %0, %1, %2, %3;" : "=l"(S2[2*i+1]) : "l"(dv.y), "l"(S2[2*i+1]), "l"(t));
                asm("fma.rn.f32x2 %0, %1, %2, %3;" : "=l"(ac[(2*i+1)&3]) : "l"(qv.y), "l"(S2[2*i+1]), "l"(ac[(2*i+1)&3]));
            }
            float p = 0.f;
#pragma unroll
            for (int j = 0; j < 4; j++) {
                float x0, x1;
                asm("mov.b64 {%0, %1}, %2;" : "=f"(x0), "=f"(x1) : "l"(ac[j]));
                p += x0 + x1;
            }
            red[bf][w][s*32 + c] = p;
        }
        __syncthreads();
#pragma unroll
        for (int j = 0; j < 2; j++) {
            int idx = tid + j*128;
            int s = idx >> 5, cc = idx & 31;
            float v = red[bf][0][s*32 + cc] + red[bf][1][s*32 + cc]
                    + red[bf][2][s*32 + cc] + red[bf][3][s*32 + cc];
            op[(size_t)(t0 + s)*1024 + cc] = v;
        }
    }
}

// ---------------------------------------------------------------------------
// RMSNorm * g_norm_w * swish(g) -> fp16 for final GEMM
// ---------------------------------------------------------------------------
__global__ __launch_bounds__(128)
void epilogue_kernel(const float* __restrict__ g, const float* __restrict__ gnw)
{
    int m = blockIdx.x, wid = threadIdx.x >> 5, lane = threadIdx.x & 31;
    size_t off = (size_t)m*1024 + (size_t)wid*256 + (size_t)lane*8;

    float4 o0 = *(const float4*)(g_o + off);
    float4 o1 = *(const float4*)(g_o + off + 4);
    float ssq = o0.x*o0.x + o0.y*o0.y + o0.z*o0.z + o0.w*o0.w
              + o1.x*o1.x + o1.y*o1.y + o1.z*o1.z + o1.w*o1.w;
#pragma unroll
    for (int s = 16; s > 0; s >>= 1) ssq += __shfl_xor_sync(0xffffffffu, ssq, s);
    float rms = rsqrtf(ssq * (1.f/256.f) + 1e-5f);

    float4 gg0 = *(const float4*)(g + off);
    float4 gg1 = *(const float4*)(g + off + 4);
    const float* wv = gnw + lane*8;

    float r[8];
    r[0] = o0.x*rms*wv[0]*(gg0.x/(1.f+expf(-gg0.x)));
    r[1] = o0.y*rms*wv[1]*(gg0.y/(1.f+expf(-gg0.y)));
    r[2] = o0.z*rms*wv[2]*(gg0.z/(1.f+expf(-gg0.z)));
    r[3] = o0.w*rms*wv[3]*(gg0.w/(1.f+expf(-gg0.w)));
    r[4] = o1.x*rms*wv[4]*(gg1.x/(1.f+expf(-gg1.x)));
    r[5] = o1.y*rms*wv[5]*(gg1.y/(1.f+expf(-gg1.y)));
    r[6] = o1.z*rms*wv[6]*(gg1.z/(1.f+expf(-gg1.z)));
    r[7] = o1.w*rms*wv[7]*(gg1.w/(1.f+expf(-gg1.w)));

#pragma unroll
    for (int i = 0; i < 8; i += 2) {
        *(__half2*)(g_oh + off + i) =
            __halves2half2(__float2half_rn(r[i]), __float2half_rn(r[i+1]));
    }
}

// ---------------------------------------------------------------------------
extern "C" void kernel_launch(void* const* d_in, const int* in_sizes, int n_in,
                              void* d_out, int out_size)
{
    (void)in_sizes; (void)n_in; (void)out_size;
    const float* x     = (const float*)d_in[0];
    const float* Wq    = (const float*)d_in[1];
    const float* Wk    = (const float*)d_in[2];
    const float* Wv    = (const float*)d_in[3];
    const float* gk_w1 = (const float*)d_in[4];
    const float* gk_w2 = (const float*)d_in[5];
    const float* gk_b2 = (const float*)d_in[6];
    const float* Wg    = (const float*)d_in[7];
    const float* gnw   = (const float*)d_in[8];
    const float* Wo    = (const float*)d_in[9];
    float* out = (float*)d_out;

    __half *xh,*wa,*wo,*oh;
    float *pq,*pk,*pd,*pv,*pg;
    cudaGetSymbolAddress((void**)&xh, g_xh);
    cudaGetSymbolAddress((void**)&wa, g_wa);  cudaGetSymbolAddress((void**)&wo, g_wo);
    cudaGetSymbolAddress((void**)&oh, g_oh);
    cudaGetSymbolAddress((void**)&pq, g_q);   cudaGetSymbolAddress((void**)&pk, g_k);
    cudaGetSymbolAddress((void**)&pd, g_dcy); cudaGetSymbolAddress((void**)&pv, g_v);
    cudaGetSymbolAddress((void**)&pg, g_g);

    cudaFuncSetAttribute((const void*)hgemm1<0>, cudaFuncAttributeMaxDynamicSharedMemorySize, SMEM3);
    cudaFuncSetAttribute((const void*)hgemm1<1>, cudaFuncAttributeMaxDynamicSharedMemorySize, SMEM3);

    // conversions
    cvt_kernel<<<MM*1024/16/256, 256>>>(x, xh, MM*1024);
    wcvt_kernel<<<(1024*512/8 + 255)/256, 256>>>(Wq, 512,  0,    1024*512);
    wcvt_kernel<<<(1024*512/8 + 255)/256, 256>>>(Wk, 512,  512,  1024*512);
    wcvt_kernel<<<(1024*1024/8 + 255)/256, 256>>>(Wv, 1024, 1536, 1024*1024);
    wcvt_kernel<<<(1024*1024/8 + 255)/256, 256>>>(Wg, 1024, 2560, 1024*1024);
    weff_cvt_kernel<<<(512*1024)/256, 256>>>(gk_w1, gk_w2);
    wo_cvt_kernel<<<(1024*1024/8 + 255)/256, 256>>>(Wo, 1024*1024);

    dim3 blk(256);

    // GEMM1: packed q | k | decay | v | g   (N=3584, grid 28x256)
    hgemm1<1><<<dim3(28, MM/128), blk, SMEM3>>>(
        xh, wa, nullptr, 1024, NPACK, 1.f, gk_b2, pq, pk, pd, pv, pg);

    gla_rec_kernel<<<BB*4*8, 128>>>();
    epilogue_kernel<<<MM, 128>>>(pg, gnw);

    // GEMM2: out = o' @ Wo  (N=1024)
    hgemm1<0><<<dim3(8, MM/128), blk, SMEM3>>>(
        oh, wo, out, 1024, 1024, 1.f, nullptr,
        nullptr, nullptr, nullptr, nullptr, nullptr);
}